// round 3
// baseline (speedup 1.0000x reference)
#include <cuda_runtime.h>
#include <cuda_bf16.h>
#include <cstddef>

// Problem constants
#define NN_ 8192
#define MM_ 4096
#define EE_ 512

// Scratch (allocation-free rule: __device__ globals)
__device__ float g_Q [NN_ * EE_];
__device__ float g_Kv[NN_ * EE_];
__device__ float g_Vv[NN_ * EE_];
__device__ float g_Ko[MM_ * EE_];
__device__ float g_Vo[MM_ * EE_];
__device__ float g_S [(size_t)NN_ * MM_];
__device__ float g_O [NN_ * EE_];
__device__ float g_self[NN_];
__device__ float g_w0 [NN_];

// ---------------------------------------------------------------------------
// NT GEMM: C[M,N] = A[M,K] * B[N,K]^T   (both K-major; classic sgemm)
// BM=BN=128, BK=8, 256 threads, 8x8 thread tile, register prefetch.
// ---------------------------------------------------------------------------
__global__ __launch_bounds__(256, 2) void sgemm_nt(
    const float* __restrict__ A, const float* __restrict__ B,
    float* __restrict__ C, int M, int N, int K)
{
    constexpr int BM = 128, BN = 128, BK = 8, TM = 8, TN = 8;
    __shared__ float As[BK][BM];
    __shared__ float Bs[BK][BN];

    const int tid = threadIdx.x;
    const int tx  = tid & 15;   // 16 across N
    const int ty  = tid >> 4;   // 16 down M
    const int row0 = blockIdx.y * BM;
    const int col0 = blockIdx.x * BN;

    const int lr = tid >> 1;         // 0..127
    const int lk = (tid & 1) * 4;    // 0 or 4

    const float* Aptr = A + (size_t)(row0 + lr) * K + lk;
    const float* Bptr = B + (size_t)(col0 + lr) * K + lk;

    float acc[TM][TN];
#pragma unroll
    for (int i = 0; i < TM; ++i)
#pragma unroll
        for (int j = 0; j < TN; ++j) acc[i][j] = 0.f;

    float4 a4 = *(const float4*)(Aptr);
    float4 b4 = *(const float4*)(Bptr);

    for (int k0 = 0; k0 < K; k0 += BK) {
        As[lk + 0][lr] = a4.x; As[lk + 1][lr] = a4.y;
        As[lk + 2][lr] = a4.z; As[lk + 3][lr] = a4.w;
        Bs[lk + 0][lr] = b4.x; Bs[lk + 1][lr] = b4.y;
        Bs[lk + 2][lr] = b4.z; Bs[lk + 3][lr] = b4.w;
        __syncthreads();

        float4 a4n = make_float4(0.f, 0.f, 0.f, 0.f);
        float4 b4n = make_float4(0.f, 0.f, 0.f, 0.f);
        if (k0 + BK < K) {
            a4n = *(const float4*)(Aptr + k0 + BK);
            b4n = *(const float4*)(Bptr + k0 + BK);
        }

#pragma unroll
        for (int k = 0; k < BK; ++k) {
            float ar[TM], br[TN];
#pragma unroll
            for (int i = 0; i < TM; ++i) ar[i] = As[k][ty * TM + i];
#pragma unroll
            for (int j = 0; j < TN; ++j) br[j] = Bs[k][tx * TN + j];
#pragma unroll
            for (int i = 0; i < TM; ++i)
#pragma unroll
                for (int j = 0; j < TN; ++j)
                    acc[i][j] = fmaf(ar[i], br[j], acc[i][j]);
        }
        __syncthreads();
        a4 = a4n; b4 = b4n;
    }

#pragma unroll
    for (int i = 0; i < TM; ++i) {
        float* Crow = C + (size_t)(row0 + ty * TM + i) * N + col0 + tx * TN;
        float4 o0 = make_float4(acc[i][0], acc[i][1], acc[i][2], acc[i][3]);
        float4 o1 = make_float4(acc[i][4], acc[i][5], acc[i][6], acc[i][7]);
        *(float4*)(Crow)     = o0;
        *(float4*)(Crow + 4) = o1;
    }
}

// ---------------------------------------------------------------------------
// NN GEMM: C[M,N] = A[M,K] * B[K,N]   (A K-major, B N-major)
// ---------------------------------------------------------------------------
__global__ __launch_bounds__(256, 2) void sgemm_nn(
    const float* __restrict__ A, const float* __restrict__ B,
    float* __restrict__ C, int M, int N, int K)
{
    constexpr int BM = 128, BN = 128, BK = 8, TM = 8, TN = 8;
    __shared__ float As[BK][BM];
    __shared__ float Bs[BK][BN];

    const int tid = threadIdx.x;
    const int tx  = tid & 15;
    const int ty  = tid >> 4;
    const int row0 = blockIdx.y * BM;
    const int col0 = blockIdx.x * BN;

    const int lr = tid >> 1;         // A: 0..127 rows
    const int lk = (tid & 1) * 4;    // A: k offset
    const int br_ = tid >> 5;        // B: 0..7 k-rows
    const int bc_ = (tid & 31) * 4;  // B: 0..124 n-cols

    const float* Aptr = A + (size_t)(row0 + lr) * K + lk;

    float acc[TM][TN];
#pragma unroll
    for (int i = 0; i < TM; ++i)
#pragma unroll
        for (int j = 0; j < TN; ++j) acc[i][j] = 0.f;

    float4 a4 = *(const float4*)(Aptr);
    float4 b4 = *(const float4*)(B + (size_t)(br_)*N + col0 + bc_);

    for (int k0 = 0; k0 < K; k0 += BK) {
        As[lk + 0][lr] = a4.x; As[lk + 1][lr] = a4.y;
        As[lk + 2][lr] = a4.z; As[lk + 3][lr] = a4.w;
        *(float4*)&Bs[br_][bc_] = b4;
        __syncthreads();

        float4 a4n = make_float4(0.f, 0.f, 0.f, 0.f);
        float4 b4n = make_float4(0.f, 0.f, 0.f, 0.f);
        if (k0 + BK < K) {
            a4n = *(const float4*)(Aptr + k0 + BK);
            b4n = *(const float4*)(B + (size_t)(k0 + BK + br_) * N + col0 + bc_);
        }

#pragma unroll
        for (int k = 0; k < BK; ++k) {
            float ar[TM], br2[TN];
#pragma unroll
            for (int i = 0; i < TM; ++i) ar[i] = As[k][ty * TM + i];
#pragma unroll
            for (int j = 0; j < TN; ++j) br2[j] = Bs[k][tx * TN + j];
#pragma unroll
            for (int i = 0; i < TM; ++i)
#pragma unroll
                for (int j = 0; j < TN; ++j)
                    acc[i][j] = fmaf(ar[i], br2[j], acc[i][j]);
        }
        __syncthreads();
        a4 = a4n; b4 = b4n;
    }

#pragma unroll
    for (int i = 0; i < TM; ++i) {
        float* Crow = C + (size_t)(row0 + ty * TM + i) * N + col0 + tx * TN;
        float4 o0 = make_float4(acc[i][0], acc[i][1], acc[i][2], acc[i][3]);
        float4 o1 = make_float4(acc[i][4], acc[i][5], acc[i][6], acc[i][7]);
        *(float4*)(Crow)     = o0;
        *(float4*)(Crow + 4) = o1;
    }
}

// ---------------------------------------------------------------------------
// Diagonal self score: self[i] = dot(Q[i,:], Kv[i,:]), E=512. 8 warps/block.
// ---------------------------------------------------------------------------
__global__ __launch_bounds__(256) void diag_dot(
    const float* __restrict__ Q, const float* __restrict__ Kv,
    float* __restrict__ selfv)
{
    const int warp = threadIdx.x >> 5;
    const int lane = threadIdx.x & 31;
    const int row  = blockIdx.x * 8 + warp;
    const float4* q = (const float4*)(Q  + (size_t)row * EE_);
    const float4* k = (const float4*)(Kv + (size_t)row * EE_);
    float s = 0.f;
#pragma unroll
    for (int i = lane; i < EE_ / 4; i += 32) {
        float4 a = q[i], b = k[i];
        s = fmaf(a.x, b.x, s); s = fmaf(a.y, b.y, s);
        s = fmaf(a.z, b.z, s); s = fmaf(a.w, b.w, s);
    }
#pragma unroll
    for (int o = 16; o; o >>= 1) s += __shfl_xor_sync(0xffffffffu, s, o);
    if (lane == 0) selfv[row] = s;
}

// ---------------------------------------------------------------------------
// Row softmax over [self | S-row(4096)] / T. One block per row; S rewritten
// in-place to normalized weights, self-weight to w0. Row held in registers.
// ---------------------------------------------------------------------------
__global__ __launch_bounds__(256) void softmax_rows(
    float* __restrict__ S, const float* __restrict__ selfv,
    float* __restrict__ w0)
{
    const int row  = blockIdx.x;
    const int tid  = threadIdx.x;
    const int lane = tid & 31, wid = tid >> 5;
    float* Srow = S + (size_t)row * MM_;

    float4 v[4];
#pragma unroll
    for (int g = 0; g < 4; ++g)
        v[g] = *(float4*)(Srow + 4 * (tid + 256 * g));

    const float sv = selfv[row];
    float m = -3.4e38f;
#pragma unroll
    for (int g = 0; g < 4; ++g)
        m = fmaxf(m, fmaxf(fmaxf(v[g].x, v[g].y), fmaxf(v[g].z, v[g].w)));
#pragma unroll
    for (int o = 16; o; o >>= 1) m = fmaxf(m, __shfl_xor_sync(0xffffffffu, m, o));

    __shared__ float smax[8], ssum[8], sbc[2];
    if (lane == 0) smax[wid] = m;
    __syncthreads();
    if (tid == 0) {
        float mm = sv;
#pragma unroll
        for (int i = 0; i < 8; ++i) mm = fmaxf(mm, smax[i]);
        sbc[0] = mm;
    }
    __syncthreads();
    m = sbc[0];

    const float invT = 0.044194173824159216f;  // 1/sqrt(512)
    float s = 0.f;
#pragma unroll
    for (int g = 0; g < 4; ++g) {
        v[g].x = __expf((v[g].x - m) * invT); s += v[g].x;
        v[g].y = __expf((v[g].y - m) * invT); s += v[g].y;
        v[g].z = __expf((v[g].z - m) * invT); s += v[g].z;
        v[g].w = __expf((v[g].w - m) * invT); s += v[g].w;
    }
#pragma unroll
    for (int o = 16; o; o >>= 1) s += __shfl_xor_sync(0xffffffffu, s, o);
    if (lane == 0) ssum[wid] = s;
    __syncthreads();
    if (tid == 0) {
        float es  = __expf((sv - m) * invT);
        float tot = es;
#pragma unroll
        for (int i = 0; i < 8; ++i) tot += ssum[i];
        sbc[1]  = 1.f / tot;
        w0[row] = es / tot;
    }
    __syncthreads();
    const float invZ = sbc[1];
#pragma unroll
    for (int g = 0; g < 4; ++g) {
        v[g].x *= invZ; v[g].y *= invZ; v[g].z *= invZ; v[g].w *= invZ;
        *(float4*)(Srow + 4 * (tid + 256 * g)) = v[g];
    }
}

// ---------------------------------------------------------------------------
// Epilogue: x = O + w0*Vv + v_code;  out = LayerNorm(x)*gamma + beta
// One block (128 thr) per row; 4 elems/thread.
// ---------------------------------------------------------------------------
__global__ __launch_bounds__(128) void ln_residual(
    const float* __restrict__ O, const float* __restrict__ Vv,
    const float* __restrict__ vcode, const float* __restrict__ w0,
    const float* __restrict__ gamma, const float* __restrict__ beta,
    float* __restrict__ out)
{
    const int row  = blockIdx.x;
    const int tid  = threadIdx.x;
    const int lane = tid & 31, wid = tid >> 5;
    const size_t base = (size_t)row * EE_ + tid * 4;
    const float w = w0[row];

    float4 o  = *(const float4*)(O + base);
    float4 vv = *(const float4*)(Vv + base);
    float4 vc = *(const float4*)(vcode + base);
    float4 x;
    x.x = fmaf(w, vv.x, o.x) + vc.x;
    x.y = fmaf(w, vv.y, o.y) + vc.y;
    x.z = fmaf(w, vv.z, o.z) + vc.z;
    x.w = fmaf(w, vv.w, o.w) + vc.w;

    __shared__ float sred[4];
    float s = x.x + x.y + x.z + x.w;
#pragma unroll
    for (int o2 = 16; o2; o2 >>= 1) s += __shfl_xor_sync(0xffffffffu, s, o2);
    if (lane == 0) sred[wid] = s;
    __syncthreads();
    const float mu = (sred[0] + sred[1] + sred[2] + sred[3]) * (1.f / 512.f);

    float4 d;
    d.x = x.x - mu; d.y = x.y - mu; d.z = x.z - mu; d.w = x.w - mu;
    float s2 = d.x * d.x + d.y * d.y + d.z * d.z + d.w * d.w;
#pragma unroll
    for (int o2 = 16; o2; o2 >>= 1) s2 += __shfl_xor_sync(0xffffffffu, s2, o2);
    __syncthreads();
    if (lane == 0) sred[wid] = s2;
    __syncthreads();
    const float var = (sred[0] + sred[1] + sred[2] + sred[3]) * (1.f / 512.f);
    const float r = rsqrtf(var + 1e-6f);

    float4 g4 = *(const float4*)(gamma + tid * 4);
    float4 b4 = *(const float4*)(beta + tid * 4);
    float4 y;
    y.x = fmaf(d.x * r, g4.x, b4.x);
    y.y = fmaf(d.y * r, g4.y, b4.y);
    y.z = fmaf(d.z * r, g4.z, b4.z);
    y.w = fmaf(d.w * r, g4.w, b4.w);
    *(float4*)(out + base) = y;
}

// ---------------------------------------------------------------------------
extern "C" void kernel_launch(void* const* d_in, const int* in_sizes, int n_in,
                              void* d_out, int out_size)
{
    const float* v_code   = (const float*)d_in[0];
    const float* obs_code = (const float*)d_in[1];
    const float* Wq       = (const float*)d_in[2];
    const float* Wk       = (const float*)d_in[3];
    const float* Wv       = (const float*)d_in[4];
    const float* gamma    = (const float*)d_in[5];
    const float* beta     = (const float*)d_in[6];
    float* out = (float*)d_out;

    float *Q, *Kv, *Vv, *Ko, *Vo, *S, *O, *selfv, *w0;
    cudaGetSymbolAddress((void**)&Q,     g_Q);
    cudaGetSymbolAddress((void**)&Kv,    g_Kv);
    cudaGetSymbolAddress((void**)&Vv,    g_Vv);
    cudaGetSymbolAddress((void**)&Ko,    g_Ko);
    cudaGetSymbolAddress((void**)&Vo,    g_Vo);
    cudaGetSymbolAddress((void**)&S,     g_S);
    cudaGetSymbolAddress((void**)&O,     g_O);
    cudaGetSymbolAddress((void**)&selfv, g_self);
    cudaGetSymbolAddress((void**)&w0,    g_w0);

    // Projections (NT: y = x @ W^T)
    sgemm_nt<<<dim3(EE_ / 128, NN_ / 128), 256>>>(v_code,   Wq, Q,  NN_, EE_, EE_);
    sgemm_nt<<<dim3(EE_ / 128, NN_ / 128), 256>>>(v_code,   Wk, Kv, NN_, EE_, EE_);
    sgemm_nt<<<dim3(EE_ / 128, NN_ / 128), 256>>>(v_code,   Wv, Vv, NN_, EE_, EE_);
    sgemm_nt<<<dim3(EE_ / 128, MM_ / 128), 256>>>(obs_code, Wk, Ko, MM_, EE_, EE_);
    sgemm_nt<<<dim3(EE_ / 128, MM_ / 128), 256>>>(obs_code, Wv, Vo, MM_, EE_, EE_);

    // Self (diagonal) score
    diag_dot<<<NN_ / 8, 256>>>(Q, Kv, selfv);

    // Scores: S = Q @ Ko^T  [8192, 4096]
    sgemm_nt<<<dim3(MM_ / 128, NN_ / 128), 256>>>(Q, Ko, S, NN_, MM_, EE_);

    // Softmax rows (in place), produce w0
    softmax_rows<<<NN_, 256>>>(S, selfv, w0);

    // O = P @ Vo  [8192, 512]
    sgemm_nn<<<dim3(EE_ / 128, NN_ / 128), 256>>>(S, Vo, O, NN_, EE_, MM_);

    // Residual + self-value + LayerNorm
    ln_residual<<<NN_, 128>>>(O, Vv, v_code, w0, gamma, beta, out);
}

// round 4
// speedup vs baseline: 2.9629x; 2.9629x over previous
#include <cuda_runtime.h>
#include <cuda_bf16.h>
#include <cstdint>
#include <cstddef>

#define NN_ 8192
#define MM_ 4096
#define EE_ 512

// ---------------- scratch (__device__ globals; no allocation) ----------------
__device__ __nv_bfloat16 g_vcode_bf[NN_ * EE_];
__device__ __nv_bfloat16 g_obs_bf  [MM_ * EE_];
__device__ __nv_bfloat16 g_Wq_bf   [EE_ * EE_];
__device__ __nv_bfloat16 g_Wk_bf   [EE_ * EE_];
__device__ __nv_bfloat16 g_Wv_bf   [EE_ * EE_];
__device__ __nv_bfloat16 g_Q       [NN_ * EE_];
__device__ __nv_bfloat16 g_Kv      [NN_ * EE_];
__device__ float         g_Vv      [NN_ * EE_];
__device__ __nv_bfloat16 g_Ko      [MM_ * EE_];
__device__ __nv_bfloat16 g_VoT     [EE_ * MM_];   // [E, M] = obs_value^T
__device__ __nv_bfloat16 g_S       [(size_t)NN_ * MM_];
__device__ float         g_O       [NN_ * EE_];
__device__ float         g_self    [NN_];
__device__ float         g_w0      [NN_];

// ---------------------------------------------------------------------------
// float -> bf16 conversion, 4 elems/thread
// ---------------------------------------------------------------------------
__global__ void cvt_bf16(const float* __restrict__ in,
                         __nv_bfloat16* __restrict__ out, int n4)
{
    int i = blockIdx.x * blockDim.x + threadIdx.x;
    if (i < n4) {
        float4 v = ((const float4*)in)[i];
        ((__nv_bfloat162*)out)[2 * i]     = __floats2bfloat162_rn(v.x, v.y);
        ((__nv_bfloat162*)out)[2 * i + 1] = __floats2bfloat162_rn(v.z, v.w);
    }
}

// ---------------------------------------------------------------------------
// bf16 NT GEMM with tensor cores: C[M,N] = A[M,K] * B[N,K]^T, fp32 accum.
// BM=BN=128, BK=32, 256 threads (8 warps as 2x4 -> warp tile 64x32),
// mma.sync.m16n8k16, cp.async double-buffered smem.
// ---------------------------------------------------------------------------
__device__ __forceinline__ void cp16(void* smem, const void* gmem)
{
    uint32_t s = (uint32_t)__cvta_generic_to_shared(smem);
    asm volatile("cp.async.cg.shared.global [%0], [%1], 16;\n"
                 :: "r"(s), "l"(gmem));
}

__device__ __forceinline__ void store_pair(float* p, float x, float y)
{
    *(float2*)p = make_float2(x, y);
}
__device__ __forceinline__ void store_pair(__nv_bfloat16* p, float x, float y)
{
    *(__nv_bfloat162*)p = __floats2bfloat162_rn(x, y);
}

template <typename OutT>
__global__ __launch_bounds__(256, 2) void gemm_bf16_nt(
    const __nv_bfloat16* __restrict__ A,
    const __nv_bfloat16* __restrict__ B,
    OutT* __restrict__ C, int M, int N, int K)
{
    constexpr int BM = 128, BN = 128, BK = 32;
    constexpr int PITCH = 40;  // elements (80B) -> conflict-free frag loads
    __shared__ __nv_bfloat16 As[2][BM][PITCH];
    __shared__ __nv_bfloat16 Bs[2][BN][PITCH];

    const int tid  = threadIdx.x;
    const int wid  = tid >> 5, lane = tid & 31;
    const int wm   = (wid >> 2) * 64;   // warp M offset: 0/64
    const int wn   = (wid & 3) * 32;    // warp N offset: 0/32/64/96
    const int gID  = lane >> 2;         // 0..7
    const int tID  = lane & 3;          // 0..3
    const int row0 = blockIdx.y * BM;
    const int col0 = blockIdx.x * BN;

    // global->smem mapping: row = tid/2, two 16B chunks at (tid&1)*16 {+0,+8}
    const int lrow = tid >> 1;
    const int lcol = (tid & 1) * 16;

    float acc[4][4][4];
#pragma unroll
    for (int mi = 0; mi < 4; ++mi)
#pragma unroll
        for (int ni = 0; ni < 4; ++ni)
#pragma unroll
            for (int q = 0; q < 4; ++q) acc[mi][ni][q] = 0.f;

    auto load_stage = [&](int s, int k0) {
        const __nv_bfloat16* Ag = A + (size_t)(row0 + lrow) * K + k0 + lcol;
        cp16(&As[s][lrow][lcol],     Ag);
        cp16(&As[s][lrow][lcol + 8], Ag + 8);
        const __nv_bfloat16* Bg = B + (size_t)(col0 + lrow) * K + k0 + lcol;
        cp16(&Bs[s][lrow][lcol],     Bg);
        cp16(&Bs[s][lrow][lcol + 8], Bg + 8);
        asm volatile("cp.async.commit_group;\n" ::: "memory");
    };

    load_stage(0, 0);
    const int KT = K / BK;

    for (int kt = 0; kt < KT; ++kt) {
        asm volatile("cp.async.wait_group 0;\n" ::: "memory");
        __syncthreads();
        if (kt + 1 < KT) load_stage((kt + 1) & 1, (kt + 1) * BK);

        const int s = kt & 1;
#pragma unroll
        for (int ks = 0; ks < 2; ++ks) {
            const int kb = ks * 16;
            uint32_t a[4][4];
#pragma unroll
            for (int mi = 0; mi < 4; ++mi) {
                const int r = wm + mi * 16 + gID;
                const int c = kb + tID * 2;
                a[mi][0] = *(const uint32_t*)&As[s][r][c];
                a[mi][1] = *(const uint32_t*)&As[s][r + 8][c];
                a[mi][2] = *(const uint32_t*)&As[s][r][c + 8];
                a[mi][3] = *(const uint32_t*)&As[s][r + 8][c + 8];
            }
#pragma unroll
            for (int ni = 0; ni < 4; ++ni) {
                const int n = wn + ni * 8 + gID;
                const int c = kb + tID * 2;
                uint32_t b0 = *(const uint32_t*)&Bs[s][n][c];
                uint32_t b1 = *(const uint32_t*)&Bs[s][n][c + 8];
#pragma unroll
                for (int mi = 0; mi < 4; ++mi) {
                    asm volatile(
                        "mma.sync.aligned.m16n8k16.row.col.f32.bf16.bf16.f32 "
                        "{%0,%1,%2,%3}, {%4,%5,%6,%7}, {%8,%9}, {%0,%1,%2,%3};\n"
                        : "+f"(acc[mi][ni][0]), "+f"(acc[mi][ni][1]),
                          "+f"(acc[mi][ni][2]), "+f"(acc[mi][ni][3])
                        : "r"(a[mi][0]), "r"(a[mi][1]), "r"(a[mi][2]), "r"(a[mi][3]),
                          "r"(b0), "r"(b1));
                }
            }
        }
        __syncthreads();
    }

    // epilogue: c0,c1 -> (row, col..col+1), c2,c3 -> (row+8, col..col+1)
#pragma unroll
    for (int mi = 0; mi < 4; ++mi) {
#pragma unroll
        for (int ni = 0; ni < 4; ++ni) {
            const int r  = row0 + wm + mi * 16 + gID;
            const int cc = col0 + wn + ni * 8 + tID * 2;
            store_pair(C + (size_t)r * N + cc,       acc[mi][ni][0], acc[mi][ni][1]);
            store_pair(C + (size_t)(r + 8) * N + cc, acc[mi][ni][2], acc[mi][ni][3]);
        }
    }
}

// ---------------------------------------------------------------------------
// Diagonal self score: self[i] = dot(Q[i,:], Kv[i,:]) (bf16 in, fp32 acc)
// ---------------------------------------------------------------------------
__global__ __launch_bounds__(256) void diag_dot(
    const __nv_bfloat16* __restrict__ Q, const __nv_bfloat16* __restrict__ Kv,
    float* __restrict__ selfv)
{
    const int warp = threadIdx.x >> 5;
    const int lane = threadIdx.x & 31;
    const int row  = blockIdx.x * 8 + warp;
    const __nv_bfloat162* q = (const __nv_bfloat162*)(Q  + (size_t)row * EE_);
    const __nv_bfloat162* k = (const __nv_bfloat162*)(Kv + (size_t)row * EE_);
    float s = 0.f;
#pragma unroll
    for (int i = lane; i < EE_ / 2; i += 32) {
        float2 a = __bfloat1622float2(q[i]);
        float2 b = __bfloat1622float2(k[i]);
        s = fmaf(a.x, b.x, s);
        s = fmaf(a.y, b.y, s);
    }
#pragma unroll
    for (int o = 16; o; o >>= 1) s += __shfl_xor_sync(0xffffffffu, s, o);
    if (lane == 0) selfv[row] = s;
}

// ---------------------------------------------------------------------------
// Row softmax over [self | S-row(4096)]/T, bf16 in-place, self weight -> w0.
// 256 threads/row; 16 halves per thread held in registers.
// ---------------------------------------------------------------------------
__global__ __launch_bounds__(256) void softmax_rows(
    __nv_bfloat16* __restrict__ S, const float* __restrict__ selfv,
    float* __restrict__ w0)
{
    const int row  = blockIdx.x;
    const int tid  = threadIdx.x;
    const int lane = tid & 31, wid = tid >> 5;
    uint4* p = (uint4*)(S + (size_t)row * MM_);

    uint4 u[2];
    u[0] = p[tid];
    u[1] = p[tid + 256];

    float f[16];
#pragma unroll
    for (int g = 0; g < 2; ++g) {
        const uint32_t* w4 = (const uint32_t*)&u[g];
#pragma unroll
        for (int j = 0; j < 4; ++j) {
            float2 t = __bfloat1622float2(*(const __nv_bfloat162*)&w4[j]);
            f[g * 8 + j * 2]     = t.x;
            f[g * 8 + j * 2 + 1] = t.y;
        }
    }

    const float sv = selfv[row];
    float m = -3.4e38f;
#pragma unroll
    for (int i = 0; i < 16; ++i) m = fmaxf(m, f[i]);
#pragma unroll
    for (int o = 16; o; o >>= 1) m = fmaxf(m, __shfl_xor_sync(0xffffffffu, m, o));

    __shared__ float smax[8], ssum[8], sbc[2];
    if (lane == 0) smax[wid] = m;
    __syncthreads();
    if (tid == 0) {
        float mm = sv;
#pragma unroll
        for (int i = 0; i < 8; ++i) mm = fmaxf(mm, smax[i]);
        sbc[0] = mm;
    }
    __syncthreads();
    m = sbc[0];

    const float invT = 0.044194173824159216f;  // 1/sqrt(512)
    float s = 0.f;
#pragma unroll
    for (int i = 0; i < 16; ++i) {
        f[i] = __expf((f[i] - m) * invT);
        s += f[i];
    }
#pragma unroll
    for (int o = 16; o; o >>= 1) s += __shfl_xor_sync(0xffffffffu, s, o);
    if (lane == 0) ssum[wid] = s;
    __syncthreads();
    if (tid == 0) {
        float es  = __expf((sv - m) * invT);
        float tot = es;
#pragma unroll
        for (int i = 0; i < 8; ++i) tot += ssum[i];
        sbc[1]  = 1.f / tot;
        w0[row] = es / tot;
    }
    __syncthreads();
    const float invZ = sbc[1];

#pragma unroll
    for (int g = 0; g < 2; ++g) {
        uint32_t* w4 = (uint32_t*)&u[g];
#pragma unroll
        for (int j = 0; j < 4; ++j) {
            __nv_bfloat162 h = __floats2bfloat162_rn(f[g * 8 + j * 2] * invZ,
                                                     f[g * 8 + j * 2 + 1] * invZ);
            w4[j] = *(const uint32_t*)&h;
        }
    }
    p[tid]       = u[0];
    p[tid + 256] = u[1];
}

// ---------------------------------------------------------------------------
// Epilogue: x = O + w0*Vv + v_code; out = LayerNorm(x)*gamma + beta (fp32)
// ---------------------------------------------------------------------------
__global__ __launch_bounds__(128) void ln_residual(
    const float* __restrict__ O, const float* __restrict__ Vv,
    const float* __restrict__ vcode, const float* __restrict__ w0,
    const float* __restrict__ gamma, const float* __restrict__ beta,
    float* __restrict__ out)
{
    const int row  = blockIdx.x;
    const int tid  = threadIdx.x;
    const int lane = tid & 31, wid = tid >> 5;
    const size_t base = (size_t)row * EE_ + tid * 4;
    const float w = w0[row];

    float4 o  = *(const float4*)(O + base);
    float4 vv = *(const float4*)(Vv + base);
    float4 vc = *(const float4*)(vcode + base);
    float4 x;
    x.x = fmaf(w, vv.x, o.x) + vc.x;
    x.y = fmaf(w, vv.y, o.y) + vc.y;
    x.z = fmaf(w, vv.z, o.z) + vc.z;
    x.w = fmaf(w, vv.w, o.w) + vc.w;

    __shared__ float sred[4];
    float s = x.x + x.y + x.z + x.w;
#pragma unroll
    for (int o2 = 16; o2; o2 >>= 1) s += __shfl_xor_sync(0xffffffffu, s, o2);
    if (lane == 0) sred[wid] = s;
    __syncthreads();
    const float mu = (sred[0] + sred[1] + sred[2] + sred[3]) * (1.f / 512.f);

    float4 d;
    d.x = x.x - mu; d.y = x.y - mu; d.z = x.z - mu; d.w = x.w - mu;
    float s2 = d.x * d.x + d.y * d.y + d.z * d.z + d.w * d.w;
#pragma unroll
    for (int o2 = 16; o2; o2 >>= 1) s2 += __shfl_xor_sync(0xffffffffu, s2, o2);
    __syncthreads();
    if (lane == 0) sred[wid] = s2;
    __syncthreads();
    const float var = (sred[0] + sred[1] + sred[2] + sred[3]) * (1.f / 512.f);
    const float r = rsqrtf(var + 1e-6f);

    float4 g4 = *(const float4*)(gamma + tid * 4);
    float4 b4 = *(const float4*)(beta + tid * 4);
    float4 y;
    y.x = fmaf(d.x * r, g4.x, b4.x);
    y.y = fmaf(d.y * r, g4.y, b4.y);
    y.z = fmaf(d.z * r, g4.z, b4.z);
    y.w = fmaf(d.w * r, g4.w, b4.w);
    *(float4*)(out + base) = y;
}

// ---------------------------------------------------------------------------
extern "C" void kernel_launch(void* const* d_in, const int* in_sizes, int n_in,
                              void* d_out, int out_size)
{
    const float* v_code   = (const float*)d_in[0];
    const float* obs_code = (const float*)d_in[1];
    const float* Wq       = (const float*)d_in[2];
    const float* Wk       = (const float*)d_in[3];
    const float* Wv       = (const float*)d_in[4];
    const float* gamma    = (const float*)d_in[5];
    const float* beta     = (const float*)d_in[6];
    float* out = (float*)d_out;

    __nv_bfloat16 *vcb, *obb, *wqb, *wkb, *wvb, *Q, *Kv, *Ko, *VoT, *S;
    float *Vv, *O, *selfv, *w0;
    cudaGetSymbolAddress((void**)&vcb,   g_vcode_bf);
    cudaGetSymbolAddress((void**)&obb,   g_obs_bf);
    cudaGetSymbolAddress((void**)&wqb,   g_Wq_bf);
    cudaGetSymbolAddress((void**)&wkb,   g_Wk_bf);
    cudaGetSymbolAddress((void**)&wvb,   g_Wv_bf);
    cudaGetSymbolAddress((void**)&Q,     g_Q);
    cudaGetSymbolAddress((void**)&Kv,    g_Kv);
    cudaGetSymbolAddress((void**)&Vv,    g_Vv);
    cudaGetSymbolAddress((void**)&Ko,    g_Ko);
    cudaGetSymbolAddress((void**)&VoT,   g_VoT);
    cudaGetSymbolAddress((void**)&S,     g_S);
    cudaGetSymbolAddress((void**)&O,     g_O);
    cudaGetSymbolAddress((void**)&selfv, g_self);
    cudaGetSymbolAddress((void**)&w0,    g_w0);

    // bf16 conversions
    cvt_bf16<<<(NN_ * EE_ / 4 + 255) / 256, 256>>>(v_code,   vcb, NN_ * EE_ / 4);
    cvt_bf16<<<(MM_ * EE_ / 4 + 255) / 256, 256>>>(obs_code, obb, MM_ * EE_ / 4);
    cvt_bf16<<<(EE_ * EE_ / 4 + 255) / 256, 256>>>(Wq, wqb, EE_ * EE_ / 4);
    cvt_bf16<<<(EE_ * EE_ / 4 + 255) / 256, 256>>>(Wk, wkb, EE_ * EE_ / 4);
    cvt_bf16<<<(EE_ * EE_ / 4 + 255) / 256, 256>>>(Wv, wvb, EE_ * EE_ / 4);

    // Projections: y = x @ W^T  (NT), bf16 out except Vv (fp32, epilogue use)
    gemm_bf16_nt<__nv_bfloat16><<<dim3(EE_ / 128, NN_ / 128), 256>>>(vcb, wqb, Q,  NN_, EE_, EE_);
    gemm_bf16_nt<__nv_bfloat16><<<dim3(EE_ / 128, NN_ / 128), 256>>>(vcb, wkb, Kv, NN_, EE_, EE_);
    gemm_bf16_nt<float>        <<<dim3(EE_ / 128, NN_ / 128), 256>>>(vcb, wvb, Vv, NN_, EE_, EE_);
    gemm_bf16_nt<__nv_bfloat16><<<dim3(EE_ / 128, MM_ / 128), 256>>>(obb, wkb, Ko, MM_, EE_, EE_);
    // VoT[e,m] = sum_k Wv[e,k]*obs_code[m,k]  -> obs_value transposed, NT form
    gemm_bf16_nt<__nv_bfloat16><<<dim3(MM_ / 128, EE_ / 128), 256>>>(wvb, obb, VoT, EE_, MM_, EE_);

    // Self (diagonal) score
    diag_dot<<<NN_ / 8, 256>>>(Q, Kv, selfv);

    // Scores: S = Q @ Ko^T  [8192, 4096], bf16 logits
    gemm_bf16_nt<__nv_bfloat16><<<dim3(MM_ / 128, NN_ / 128), 256>>>(Q, Ko, S, NN_, MM_, EE_);

    // Softmax rows (bf16 in-place), produce w0
    softmax_rows<<<NN_, 256>>>(S, selfv, w0);

    // O = P @ VoT^T  [8192, 512], fp32 out
    gemm_bf16_nt<float><<<dim3(EE_ / 128, NN_ / 128), 256>>>(S, VoT, O, NN_, EE_, MM_);

    // Residual + self-value + LayerNorm
    ln_residual<<<NN_, 128>>>(O, Vv, v_code, w0, gamma, beta, out);
}

// round 7
// speedup vs baseline: 6.6781x; 2.2539x over previous
#include <cuda_runtime.h>
#include <cuda_bf16.h>
#include <cstdint>
#include <cstddef>

#define NN_ 8192
#define MM_ 4096
#define EE_ 512

// ---------------- scratch (__device__ globals; no allocation) ----------------
__device__ __nv_bfloat16 g_vcode_bf[NN_ * EE_];
__device__ __nv_bfloat16 g_obs_bf  [MM_ * EE_];
__device__ __nv_bfloat16 g_Wq_bf   [EE_ * EE_];
__device__ __nv_bfloat16 g_Wk_bf   [EE_ * EE_];
__device__ __nv_bfloat16 g_Wv_bf   [EE_ * EE_];
__device__ __nv_bfloat16 g_Q       [NN_ * EE_];
__device__ __nv_bfloat16 g_Kv      [NN_ * EE_];
__device__ float         g_Vv      [NN_ * EE_];
__device__ __nv_bfloat16 g_Ko      [MM_ * EE_];
__device__ __nv_bfloat16 g_VoT     [EE_ * MM_];   // [E, M] = obs_value^T
__device__ __nv_bfloat16 g_S       [(size_t)NN_ * MM_];
__device__ float         g_O       [NN_ * EE_];
__device__ float         g_self    [NN_];
__device__ float         g_w0      [NN_];

// ------------------------------- PTX helpers -------------------------------
__device__ __forceinline__ uint32_t smem_u32(const void* p) {
    uint32_t a;
    asm("{ .reg .u64 t; cvta.to.shared.u64 t, %1; cvt.u32.u64 %0, t; }"
        : "=r"(a) : "l"(p));
    return a;
}
__device__ __forceinline__ void cp16(uint32_t smem, const void* gmem) {
    asm volatile("cp.async.cg.shared.global [%0], [%1], 16;\n" :: "r"(smem), "l"(gmem));
}
#define CP_COMMIT() asm volatile("cp.async.commit_group;\n" ::: "memory")

__device__ __forceinline__ void ldm_x4(uint32_t& r0, uint32_t& r1,
                                       uint32_t& r2, uint32_t& r3, uint32_t addr) {
    asm volatile("ldmatrix.sync.aligned.m8n8.x4.shared.b16 {%0,%1,%2,%3}, [%4];"
                 : "=r"(r0), "=r"(r1), "=r"(r2), "=r"(r3) : "r"(addr));
}

__device__ __forceinline__ uint32_t swz(uint32_t off) {
    return off ^ ((off >> 3) & 0x70);
}

__device__ __forceinline__ void store_pair(float* p, float x, float y) {
    *(float2*)p = make_float2(x, y);
}
__device__ __forceinline__ void store_pair(__nv_bfloat16* p, float x, float y) {
    *(__nv_bfloat162*)p = __floats2bfloat162_rn(x, y);
}

// ---------------------------------------------------------------------------
// bf16 NT GEMM (mma.sync tensor cores): C[M,N] = A[M,K] * B[N,K]^T, fp32 acc.
// BM=BN=128, BK=64, 3-stage cp.async, 256 threads, warp tile 64x32,
// ldmatrix.x4 fragment loads from XOR-SW128 swizzled smem.
// ---------------------------------------------------------------------------
#define GBM 128
#define GBN 128
#define GBK 64
#define GSTAGES 3
#define A_STG 16384                      // 128 rows * 128B
#define B_STG 16384
#define STG_B (A_STG + B_STG)            // 32768
#define G_SMEM_TOTAL (GSTAGES * STG_B)   // 98304

template <typename OutT>
__global__ __launch_bounds__(256, 2) void gemm_bf16_nt(
    const __nv_bfloat16* __restrict__ A,
    const __nv_bfloat16* __restrict__ B,
    OutT* __restrict__ C, int M, int N, int K)
{
    extern __shared__ char smem[];
    const uint32_t sb = smem_u32(smem);

    const int tid  = threadIdx.x;
    const int wid  = tid >> 5, lane = tid & 31;
    const int wm   = (wid >> 2) * 64;   // warp M offset
    const int wn   = (wid & 3) * 32;    // warp N offset
    const int gID  = lane >> 2;
    const int tID  = lane & 3;
    const int row0 = blockIdx.y * GBM;
    const int col0 = blockIdx.x * GBN;
    const int KT   = K / GBK;

    // ldmatrix per-lane static offsets (bytes within a stage's A or B tile)
    const int lr = lane & 7;            // row within 8x8 tile
    const int lm = lane >> 3;           // matrix index 0..3
    uint32_t baseA[4], baseB[2];
#pragma unroll
    for (int mi = 0; mi < 4; ++mi)
        baseA[mi] = (uint32_t)(wm + mi * 16 + (lm & 1) * 8 + lr) * 128 + (lm >> 1) * 16;
#pragma unroll
    for (int nj = 0; nj < 2; ++nj)
        baseB[nj] = (uint32_t)(wn + nj * 16 + (lm >> 1) * 8 + lr) * 128 + (lm & 1) * 16;

    // global->smem: idx -> row idx>>3, 16B chunk idx&7
    auto load_stage = [&](int s, int k0) {
        const uint32_t abase = sb + s * STG_B;
#pragma unroll
        for (int i = 0; i < 4; ++i) {
            int idx = tid + 256 * i;
            int r = idx >> 3, ck = idx & 7;
            cp16(abase + swz(r * 128 + ck * 16),
                 A + (size_t)(row0 + r) * K + k0 + ck * 8);
        }
        const uint32_t bbase = abase + A_STG;
#pragma unroll
        for (int i = 0; i < 4; ++i) {
            int idx = tid + 256 * i;
            int r = idx >> 3, ck = idx & 7;
            cp16(bbase + swz(r * 128 + ck * 16),
                 B + (size_t)(col0 + r) * K + k0 + ck * 8);
        }
        CP_COMMIT();
    };

    float acc[4][4][4];
#pragma unroll
    for (int mi = 0; mi < 4; ++mi)
#pragma unroll
        for (int ni = 0; ni < 4; ++ni)
#pragma unroll
            for (int q = 0; q < 4; ++q) acc[mi][ni][q] = 0.f;

    load_stage(0, 0);
    load_stage(1, GBK);

    for (int kt = 0; kt < KT; ++kt) {
        const int s = kt % GSTAGES;
        if (kt == KT - 1) asm volatile("cp.async.wait_group 0;\n" ::: "memory");
        else              asm volatile("cp.async.wait_group 1;\n" ::: "memory");
        __syncthreads();
        if (kt + 2 < KT) load_stage((kt + 2) % GSTAGES, (kt + 2) * GBK);

        const uint32_t Ab = sb + s * STG_B;
        const uint32_t Bb = Ab + A_STG;
#pragma unroll
        for (int kb = 0; kb < 4; ++kb) {       // 4 x k16 steps
            const uint32_t ko = kb * 32;       // byte offset within 128B row
            uint32_t a[4][4], b[2][4];
#pragma unroll
            for (int mi = 0; mi < 4; ++mi)
                ldm_x4(a[mi][0], a[mi][1], a[mi][2], a[mi][3],
                       Ab + swz(baseA[mi] + ko));
#pragma unroll
            for (int nj = 0; nj < 2; ++nj)
                ldm_x4(b[nj][0], b[nj][1], b[nj][2], b[nj][3],
                       Bb + swz(baseB[nj] + ko));
#pragma unroll
            for (int mi = 0; mi < 4; ++mi) {
#pragma unroll
                for (int ni = 0; ni < 4; ++ni) {
                    const uint32_t b0 = b[ni >> 1][(ni & 1) * 2];
                    const uint32_t b1 = b[ni >> 1][(ni & 1) * 2 + 1];
                    asm volatile(
                        "mma.sync.aligned.m16n8k16.row.col.f32.bf16.bf16.f32 "
                        "{%0,%1,%2,%3}, {%4,%5,%6,%7}, {%8,%9}, {%0,%1,%2,%3};\n"
                        : "+f"(acc[mi][ni][0]), "+f"(acc[mi][ni][1]),
                          "+f"(acc[mi][ni][2]), "+f"(acc[mi][ni][3])
                        : "r"(a[mi][0]), "r"(a[mi][1]), "r"(a[mi][2]), "r"(a[mi][3]),
                          "r"(b0), "r"(b1));
                }
            }
        }
        __syncthreads();
    }

    // epilogue: c0,c1 -> (row, col..col+1), c2,c3 -> (row+8, col..col+1)
#pragma unroll
    for (int mi = 0; mi < 4; ++mi) {
#pragma unroll
        for (int ni = 0; ni < 4; ++ni) {
            const int r  = row0 + wm + mi * 16 + gID;
            const int cc = col0 + wn + ni * 8 + tID * 2;
            store_pair(C + (size_t)r * N + cc,       acc[mi][ni][0], acc[mi][ni][1]);
            store_pair(C + (size_t)(r + 8) * N + cc, acc[mi][ni][2], acc[mi][ni][3]);
        }
    }
}

// ---------------------------------------------------------------------------
// float -> bf16 conversion, 4 elems/thread
// ---------------------------------------------------------------------------
__global__ void cvt_bf16(const float* __restrict__ in,
                         __nv_bfloat16* __restrict__ out, int n4)
{
    int i = blockIdx.x * blockDim.x + threadIdx.x;
    if (i < n4) {
        float4 v = ((const float4*)in)[i];
        ((__nv_bfloat162*)out)[2 * i]     = __floats2bfloat162_rn(v.x, v.y);
        ((__nv_bfloat162*)out)[2 * i + 1] = __floats2bfloat162_rn(v.z, v.w);
    }
}

// ---------------------------------------------------------------------------
// Diagonal self score: self[i] = dot(Q[i,:], Kv[i,:]) (bf16 in, fp32 acc)
// ---------------------------------------------------------------------------
__global__ __launch_bounds__(256) void diag_dot(
    const __nv_bfloat16* __restrict__ Q, const __nv_bfloat16* __restrict__ Kv,
    float* __restrict__ selfv)
{
    const int warp = threadIdx.x >> 5;
    const int lane = threadIdx.x & 31;
    const int row  = blockIdx.x * 8 + warp;
    const __nv_bfloat162* q = (const __nv_bfloat162*)(Q  + (size_t)row * EE_);
    const __nv_bfloat162* k = (const __nv_bfloat162*)(Kv + (size_t)row * EE_);
    float s = 0.f;
#pragma unroll
    for (int i = lane; i < EE_ / 2; i += 32) {
        float2 a = __bfloat1622float2(q[i]);
        float2 b = __bfloat1622float2(k[i]);
        s = fmaf(a.x, b.x, s);
        s = fmaf(a.y, b.y, s);
    }
#pragma unroll
    for (int o = 16; o; o >>= 1) s += __shfl_xor_sync(0xffffffffu, s, o);
    if (lane == 0) selfv[row] = s;
}

// ---------------------------------------------------------------------------
// Row softmax over [self | S-row(4096)]/T, bf16 in-place, self weight -> w0.
// ---------------------------------------------------------------------------
__global__ __launch_bounds__(256) void softmax_rows(
    __nv_bfloat16* __restrict__ S, const float* __restrict__ selfv,
    float* __restrict__ w0)
{
    const int row  = blockIdx.x;
    const int tid  = threadIdx.x;
    const int lane = tid & 31, wid = tid >> 5;
    uint4* p = (uint4*)(S + (size_t)row * MM_);

    uint4 u[2];
    u[0] = p[tid];
    u[1] = p[tid + 256];

    float f[16];
#pragma unroll
    for (int g = 0; g < 2; ++g) {
        const uint32_t* w4 = (const uint32_t*)&u[g];
#pragma unroll
        for (int j = 0; j < 4; ++j) {
            float2 t = __bfloat1622float2(*(const __nv_bfloat162*)&w4[j]);
            f[g * 8 + j * 2]     = t.x;
            f[g * 8 + j * 2 + 1] = t.y;
        }
    }

    const float sv = selfv[row];
    float m = -3.4e38f;
#pragma unroll
    for (int i = 0; i < 16; ++i) m = fmaxf(m, f[i]);
#pragma unroll
    for (int o = 16; o; o >>= 1) m = fmaxf(m, __shfl_xor_sync(0xffffffffu, m, o));

    __shared__ float smax[8], ssum[8], sbc[2];
    if (lane == 0) smax[wid] = m;
    __syncthreads();
    if (tid == 0) {
        float mm = sv;
#pragma unroll
        for (int i = 0; i < 8; ++i) mm = fmaxf(mm, smax[i]);
        sbc[0] = mm;
    }
    __syncthreads();
    m = sbc[0];

    const float invT = 0.044194173824159216f;  // 1/sqrt(512)
    float s = 0.f;
#pragma unroll
    for (int i = 0; i < 16; ++i) {
        f[i] = __expf((f[i] - m) * invT);
        s += f[i];
    }
#pragma unroll
    for (int o = 16; o; o >>= 1) s += __shfl_xor_sync(0xffffffffu, s, o);
    if (lane == 0) ssum[wid] = s;
    __syncthreads();
    if (tid == 0) {
        float es  = __expf((sv - m) * invT);
        float tot = es;
#pragma unroll
        for (int i = 0; i < 8; ++i) tot += ssum[i];
        sbc[1]  = 1.f / tot;
        w0[row] = es / tot;
    }
    __syncthreads();
    const float invZ = sbc[1];

#pragma unroll
    for (int g = 0; g < 2; ++g) {
        uint32_t* w4 = (uint32_t*)&u[g];
#pragma unroll
        for (int j = 0; j < 4; ++j) {
            __nv_bfloat162 h = __floats2bfloat162_rn(f[g * 8 + j * 2] * invZ,
                                                     f[g * 8 + j * 2 + 1] * invZ);
            w4[j] = *(const uint32_t*)&h;
        }
    }
    p[tid]       = u[0];
    p[tid + 256] = u[1];
}

// ---------------------------------------------------------------------------
// Epilogue: x = O + w0*Vv + v_code; out = LayerNorm(x)*gamma + beta (fp32)
// ---------------------------------------------------------------------------
__global__ __launch_bounds__(128) void ln_residual(
    const float* __restrict__ O, const float* __restrict__ Vv,
    const float* __restrict__ vcode, const float* __restrict__ w0,
    const float* __restrict__ gamma, const float* __restrict__ beta,
    float* __restrict__ out)
{
    const int row  = blockIdx.x;
    const int tid  = threadIdx.x;
    const int lane = tid & 31, wid = tid >> 5;
    const size_t base = (size_t)row * EE_ + tid * 4;
    const float w = w0[row];

    float4 o  = *(const float4*)(O + base);
    float4 vv = *(const float4*)(Vv + base);
    float4 vc = *(const float4*)(vcode + base);
    float4 x;
    x.x = fmaf(w, vv.x, o.x) + vc.x;
    x.y = fmaf(w, vv.y, o.y) + vc.y;
    x.z = fmaf(w, vv.z, o.z) + vc.z;
    x.w = fmaf(w, vv.w, o.w) + vc.w;

    __shared__ float sred[4];
    float s = x.x + x.y + x.z + x.w;
#pragma unroll
    for (int o2 = 16; o2; o2 >>= 1) s += __shfl_xor_sync(0xffffffffu, s, o2);
    if (lane == 0) sred[wid] = s;
    __syncthreads();
    const float mu = (sred[0] + sred[1] + sred[2] + sred[3]) * (1.f / 512.f);

    float4 d;
    d.x = x.x - mu; d.y = x.y - mu; d.z = x.z - mu; d.w = x.w - mu;
    float s2 = d.x * d.x + d.y * d.y + d.z * d.z + d.w * d.w;
#pragma unroll
    for (int o2 = 16; o2; o2 >>= 1) s2 += __shfl_xor_sync(0xffffffffu, s2, o2);
    __syncthreads();
    if (lane == 0) sred[wid] = s2;
    __syncthreads();
    const float var = (sred[0] + sred[1] + sred[2] + sred[3]) * (1.f / 512.f);
    const float r = rsqrtf(var + 1e-6f);

    float4 g4 = *(const float4*)(gamma + tid * 4);
    float4 b4 = *(const float4*)(beta + tid * 4);
    float4 y;
    y.x = fmaf(d.x * r, g4.x, b4.x);
    y.y = fmaf(d.y * r, g4.y, b4.y);
    y.z = fmaf(d.z * r, g4.z, b4.z);
    y.w = fmaf(d.w * r, g4.w, b4.w);
    *(float4*)(out + base) = y;
}

// ---------------------------------------------------------------------------
extern "C" void kernel_launch(void* const* d_in, const int* in_sizes, int n_in,
                              void* d_out, int out_size)
{
    const float* v_code   = (const float*)d_in[0];
    const float* obs_code = (const float*)d_in[1];
    const float* Wq       = (const float*)d_in[2];
    const float* Wk       = (const float*)d_in[3];
    const float* Wv       = (const float*)d_in[4];
    const float* gamma    = (const float*)d_in[5];
    const float* beta     = (const float*)d_in[6];
    float* out = (float*)d_out;

    __nv_bfloat16 *vcb, *obb, *wqb, *wkb, *wvb, *Q, *Kv, *Ko, *VoT, *S;
    float *Vv, *O, *selfv, *w0;
    cudaGetSymbolAddress((void**)&vcb,   g_vcode_bf);
    cudaGetSymbolAddress((void**)&obb,   g_obs_bf);
    cudaGetSymbolAddress((void**)&wqb,   g_Wq_bf);
    cudaGetSymbolAddress((void**)&wkb,   g_Wk_bf);
    cudaGetSymbolAddress((void**)&wvb,   g_Wv_bf);
    cudaGetSymbolAddress((void**)&Q,     g_Q);
    cudaGetSymbolAddress((void**)&Kv,    g_Kv);
    cudaGetSymbolAddress((void**)&Vv,    g_Vv);
    cudaGetSymbolAddress((void**)&Ko,    g_Ko);
    cudaGetSymbolAddress((void**)&VoT,   g_VoT);
    cudaGetSymbolAddress((void**)&S,     g_S);
    cudaGetSymbolAddress((void**)&O,     g_O);
    cudaGetSymbolAddress((void**)&selfv, g_self);
    cudaGetSymbolAddress((void**)&w0,    g_w0);

    static bool attr_done = false;
    if (!attr_done) {
        cudaFuncSetAttribute(gemm_bf16_nt<__nv_bfloat16>,
                             cudaFuncAttributeMaxDynamicSharedMemorySize, G_SMEM_TOTAL);
        cudaFuncSetAttribute(gemm_bf16_nt<float>,
                             cudaFuncAttributeMaxDynamicSharedMemorySize, G_SMEM_TOTAL);
        attr_done = true;
    }

    // bf16 conversions
    cvt_bf16<<<(NN_ * EE_ / 4 + 255) / 256, 256>>>(v_code,   vcb, NN_ * EE_ / 4);
    cvt_bf16<<<(MM_ * EE_ / 4 + 255) / 256, 256>>>(obs_code, obb, MM_ * EE_ / 4);
    cvt_bf16<<<(EE_ * EE_ / 4 + 255) / 256, 256>>>(Wq, wqb, EE_ * EE_ / 4);
    cvt_bf16<<<(EE_ * EE_ / 4 + 255) / 256, 256>>>(Wk, wkb, EE_ * EE_ / 4);
    cvt_bf16<<<(EE_ * EE_ / 4 + 255) / 256, 256>>>(Wv, wvb, EE_ * EE_ / 4);

    // Projections: y = x @ W^T (NT), bf16 out except Vv (fp32, epilogue use)
    gemm_bf16_nt<__nv_bfloat16><<<dim3(EE_/128, NN_/128), 256, G_SMEM_TOTAL>>>(vcb, wqb, Q,  NN_, EE_, EE_);
    gemm_bf16_nt<__nv_bfloat16><<<dim3(EE_/128, NN_/128), 256, G_SMEM_TOTAL>>>(vcb, wkb, Kv, NN_, EE_, EE_);
    gemm_bf16_nt<float>        <<<dim3(EE_/128, NN_/128), 256, G_SMEM_TOTAL>>>(vcb, wvb, Vv, NN_, EE_, EE_);
    gemm_bf16_nt<__nv_bfloat16><<<dim3(EE_/128, MM_/128), 256, G_SMEM_TOTAL>>>(obb, wkb, Ko, MM_, EE_, EE_);
    // VoT[e,m] = sum_k Wv[e,k]*obs_code[m,k] -> obs_value^T, NT form
    gemm_bf16_nt<__nv_bfloat16><<<dim3(MM_/128, EE_/128), 256, G_SMEM_TOTAL>>>(wvb, obb, VoT, EE_, MM_, EE_);

    // Self (diagonal) score
    diag_dot<<<NN_ / 8, 256>>>(Q, Kv, selfv);

    // Scores: S = Q @ Ko^T [8192, 4096], bf16 logits
    gemm_bf16_nt<__nv_bfloat16><<<dim3(MM_/128, NN_/128), 256, G_SMEM_TOTAL>>>(Q, Ko, S, NN_, MM_, EE_);

    // Softmax rows (bf16 in-place), produce w0
    softmax_rows<<<NN_, 256>>>(S, selfv, w0);

    // O = P @ VoT^T [8192, 512], fp32 out
    gemm_bf16_nt<float><<<dim3(EE_/128, NN_/128), 256, G_SMEM_TOTAL>>>(S, VoT, O, NN_, EE_, MM_);

    // Residual + self-value + LayerNorm
    ln_residual<<<NN_, 128>>>(O, Vv, v_code, w0, gamma, beta, out);
}

// round 9
// speedup vs baseline: 7.0280x; 1.0524x over previous
#include <cuda_runtime.h>
#include <cuda_bf16.h>
#include <cstdint>
#include <cstddef>

#define NN_ 8192
#define MM_ 4096
#define EE_ 512

// ---------------- scratch (__device__ globals; no allocation) ----------------
__device__ __nv_bfloat16 g_vcode_bf[NN_ * EE_];
__device__ __nv_bfloat16 g_obs_bf  [MM_ * EE_];
__device__ __nv_bfloat16 g_Wcat    [3 * EE_ * EE_];         // [Wq; Wk; Wv]
__device__ __nv_bfloat16 g_QKV     [(size_t)NN_ * 3 * EE_]; // cols: Q|Kv|Vv
__device__ __nv_bfloat16 g_KoVo    [(size_t)MM_ * 2 * EE_]; // cols: Ko|Vo
__device__ __nv_bfloat16 g_VoT     [EE_ * MM_];             // [E, M]
__device__ __nv_bfloat16 g_S       [(size_t)NN_ * MM_];
__device__ float         g_Opart   [2][(size_t)NN_ * EE_];  // split-K partials
__device__ float         g_self    [NN_];
__device__ float         g_w0      [NN_];

// ------------------------------- PTX helpers -------------------------------
__device__ __forceinline__ uint32_t smem_u32(const void* p) {
    uint32_t a;
    asm("{ .reg .u64 t; cvta.to.shared.u64 t, %1; cvt.u32.u64 %0, t; }"
        : "=r"(a) : "l"(p));
    return a;
}
__device__ __forceinline__ void cp16(uint32_t smem, const void* gmem) {
    asm volatile("cp.async.cg.shared.global [%0], [%1], 16;\n" :: "r"(smem), "l"(gmem));
}
#define CP_COMMIT() asm volatile("cp.async.commit_group;\n" ::: "memory")

__device__ __forceinline__ void ldm_x4(uint32_t& r0, uint32_t& r1,
                                       uint32_t& r2, uint32_t& r3, uint32_t addr) {
    asm volatile("ldmatrix.sync.aligned.m8n8.x4.shared.b16 {%0,%1,%2,%3}, [%4];"
                 : "=r"(r0), "=r"(r1), "=r"(r2), "=r"(r3) : "r"(addr));
}
__device__ __forceinline__ uint32_t swz(uint32_t off) {
    return off ^ ((off >> 3) & 0x70);
}
__device__ __forceinline__ void store_pair(float* p, float x, float y) {
    *(float2*)p = make_float2(x, y);
}
__device__ __forceinline__ void store_pair(__nv_bfloat16* p, float x, float y) {
    *(__nv_bfloat162*)p = __floats2bfloat162_rn(x, y);
}

// ---------------------------------------------------------------------------
// bf16 NT GEMM (mma.sync): C[M,N] = A[M,K] * B[N,K]^T, fp32 acc.
// CTA tile 128x256x64, warp tile 64x64, 4-stage cp.async, 256 threads.
// Strided A/B/C. Optional split-K via gridDim.z (Ksp = per-split K length;
// C advanced by z*M*ldc).
// ---------------------------------------------------------------------------
#define GBM 128
#define GBN 256
#define GBK 64
#define A_STG 16384                      // 128 rows * 128B
#define B_STG 32768                      // 256 rows * 128B
#define STG_B (A_STG + B_STG)            // 49152
#define G_SMEM_TOTAL (4 * STG_B)         // 196608

template <typename OutT>
__global__ __launch_bounds__(256, 1) void gemm_nt(
    const __nv_bfloat16* __restrict__ A,
    const __nv_bfloat16* __restrict__ B,
    OutT* __restrict__ C,
    int M, int N, int K, int lda, int ldb, int ldc, int Ksp)
{
    extern __shared__ char smem[];
    const uint32_t sb = smem_u32(smem);

    const int tid  = threadIdx.x;
    const int wid  = tid >> 5, lane = tid & 31;
    const int wm   = (wid >> 2) * 64;   // 0/64
    const int wn   = (wid & 3) * 64;    // 0/64/128/192
    const int gID  = lane >> 2;
    const int tID  = lane & 3;
    const int row0 = blockIdx.y * GBM;
    const int col0 = blockIdx.x * GBN;
    const int KT   = K / GBK;

    // split-K offsets
    const int kz = blockIdx.z;
    A += (size_t)kz * Ksp;
    B += (size_t)kz * Ksp;
    C += (size_t)kz * (size_t)M * ldc;

    // ldmatrix per-lane static offsets (bytes within stage tile)
    const int lr = lane & 7;
    const int lm = lane >> 3;
    uint32_t baseA[4], baseB[4];
#pragma unroll
    for (int mi = 0; mi < 4; ++mi)
        baseA[mi] = (uint32_t)(wm + mi * 16 + (lm & 1) * 8 + lr) * 128 + (lm >> 1) * 16;
#pragma unroll
    for (int nj = 0; nj < 4; ++nj)
        baseB[nj] = (uint32_t)(wn + nj * 16 + (lm >> 1) * 8 + lr) * 128 + (lm & 1) * 16;

    auto load_stage = [&](int s, int k0) {
        const uint32_t abase = sb + s * STG_B;
#pragma unroll
        for (int i = 0; i < 4; ++i) {      // A: 1024 16B chunks
            int idx = tid + 256 * i;
            int r = idx >> 3, ck = idx & 7;
            cp16(abase + swz(r * 128 + ck * 16),
                 A + (size_t)(row0 + r) * lda + k0 + ck * 8);
        }
        const uint32_t bbase = abase + A_STG;
#pragma unroll
        for (int i = 0; i < 8; ++i) {      // B: 2048 16B chunks
            int idx = tid + 256 * i;
            int r = idx >> 3, ck = idx & 7;
            cp16(bbase + swz(r * 128 + ck * 16),
                 B + (size_t)(col0 + r) * ldb + k0 + ck * 8);
        }
        CP_COMMIT();
    };

    float acc[4][8][4];
#pragma unroll
    for (int mi = 0; mi < 4; ++mi)
#pragma unroll
        for (int ni = 0; ni < 8; ++ni)
#pragma unroll
            for (int q = 0; q < 4; ++q) acc[mi][ni][q] = 0.f;

    load_stage(0, 0);
    load_stage(1, GBK);
    load_stage(2, 2 * GBK);

    for (int kt = 0; kt < KT; ++kt) {
        const int s = kt & 3;
        if (kt <= KT - 3)      asm volatile("cp.async.wait_group 2;\n" ::: "memory");
        else if (kt == KT - 2) asm volatile("cp.async.wait_group 1;\n" ::: "memory");
        else                   asm volatile("cp.async.wait_group 0;\n" ::: "memory");
        __syncthreads();
        if (kt + 3 < KT) load_stage((kt + 3) & 3, (kt + 3) * GBK);

        const uint32_t Ab = sb + s * STG_B;
        const uint32_t Bb = Ab + A_STG;
#pragma unroll
        for (int kb = 0; kb < 4; ++kb) {       // 4 x k16 steps
            const uint32_t ko = kb * 32;       // byte offset in 128B row
            uint32_t a[4][4], b[4][4];
#pragma unroll
            for (int mi = 0; mi < 4; ++mi)
                ldm_x4(a[mi][0], a[mi][1], a[mi][2], a[mi][3],
                       Ab + swz(baseA[mi] + ko));
#pragma unroll
            for (int nj = 0; nj < 4; ++nj)
                ldm_x4(b[nj][0], b[nj][1], b[nj][2], b[nj][3],
                       Bb + swz(baseB[nj] + ko));
#pragma unroll
            for (int mi = 0; mi < 4; ++mi) {
#pragma unroll
                for (int ni = 0; ni < 8; ++ni) {
                    const uint32_t b0 = b[ni >> 1][(ni & 1) * 2];
                    const uint32_t b1 = b[ni >> 1][(ni & 1) * 2 + 1];
                    asm volatile(
                        "mma.sync.aligned.m16n8k16.row.col.f32.bf16.bf16.f32 "
                        "{%0,%1,%2,%3}, {%4,%5,%6,%7}, {%8,%9}, {%0,%1,%2,%3};\n"
                        : "+f"(acc[mi][ni][0]), "+f"(acc[mi][ni][1]),
                          "+f"(acc[mi][ni][2]), "+f"(acc[mi][ni][3])
                        : "r"(a[mi][0]), "r"(a[mi][1]), "r"(a[mi][2]), "r"(a[mi][3]),
                          "r"(b0), "r"(b1));
                }
            }
        }
        __syncthreads();
    }

    // epilogue
#pragma unroll
    for (int mi = 0; mi < 4; ++mi) {
#pragma unroll
        for (int ni = 0; ni < 8; ++ni) {
            const int r  = row0 + wm + mi * 16 + gID;
            const int cc = col0 + wn + ni * 8 + tID * 2;
            store_pair(C + (size_t)r * ldc + cc,       acc[mi][ni][0], acc[mi][ni][1]);
            store_pair(C + (size_t)(r + 8) * ldc + cc, acc[mi][ni][2], acc[mi][ni][3]);
        }
    }
}

// ---------------------------------------------------------------------------
// float -> bf16 conversion, 4 elems/thread
// ---------------------------------------------------------------------------
__global__ void cvt_bf16(const float* __restrict__ in,
                         __nv_bfloat16* __restrict__ out, int n4)
{
    int i = blockIdx.x * blockDim.x + threadIdx.x;
    if (i < n4) {
        float4 v = ((const float4*)in)[i];
        ((__nv_bfloat162*)out)[2 * i]     = __floats2bfloat162_rn(v.x, v.y);
        ((__nv_bfloat162*)out)[2 * i + 1] = __floats2bfloat162_rn(v.z, v.w);
    }
}

// ---------------------------------------------------------------------------
// Transpose Vo (cols 512..1023 of KoVo [4096, 1024]) -> VoT [512, 4096]
// ---------------------------------------------------------------------------
__global__ __launch_bounds__(256) void transpose_vo(
    const __nv_bfloat16* __restrict__ KoVo, __nv_bfloat16* __restrict__ VoT)
{
    __shared__ __nv_bfloat16 t[32][33];
    const int tx = threadIdx.x & 31, ty = threadIdx.x >> 5;  // 32x8
    const int m0 = blockIdx.x * 32;   // along M=4096
    const int e0 = blockIdx.y * 32;   // along E=512
#pragma unroll
    for (int p = 0; p < 4; ++p)
        t[ty + p * 8][tx] = KoVo[(size_t)(m0 + ty + p * 8) * 1024 + 512 + e0 + tx];
    __syncthreads();
#pragma unroll
    for (int p = 0; p < 4; ++p)
        VoT[(size_t)(e0 + ty + p * 8) * MM_ + m0 + tx] = t[tx][ty + p * 8];
}

// ---------------------------------------------------------------------------
// Diagonal self score: self[i] = dot(Q[i,:], Kv[i,:]) from QKV (stride 1536)
// ---------------------------------------------------------------------------
__global__ __launch_bounds__(256) void diag_dot(
    const __nv_bfloat16* __restrict__ QKV, float* __restrict__ selfv)
{
    const int warp = threadIdx.x >> 5;
    const int lane = threadIdx.x & 31;
    const int row  = blockIdx.x * 8 + warp;
    const __nv_bfloat162* q = (const __nv_bfloat162*)(QKV + (size_t)row * 1536);
    const __nv_bfloat162* k = (const __nv_bfloat162*)(QKV + (size_t)row * 1536 + 512);
    float s = 0.f;
#pragma unroll
    for (int i = lane; i < EE_ / 2; i += 32) {
        float2 a = __bfloat1622float2(q[i]);
        float2 b = __bfloat1622float2(k[i]);
        s = fmaf(a.x, b.x, s);
        s = fmaf(a.y, b.y, s);
    }
#pragma unroll
    for (int o = 16; o; o >>= 1) s += __shfl_xor_sync(0xffffffffu, s, o);
    if (lane == 0) selfv[row] = s;
}

// ---------------------------------------------------------------------------
// Row softmax over [self | S-row(4096)]/T, bf16 in-place, self weight -> w0.
// ---------------------------------------------------------------------------
__global__ __launch_bounds__(256) void softmax_rows(
    __nv_bfloat16* __restrict__ S, const float* __restrict__ selfv,
    float* __restrict__ w0)
{
    const int row  = blockIdx.x;
    const int tid  = threadIdx.x;
    const int lane = tid & 31, wid = tid >> 5;
    uint4* p = (uint4*)(S + (size_t)row * MM_);

    uint4 u[2];
    u[0] = p[tid];
    u[1] = p[tid + 256];

    float f[16];
#pragma unroll
    for (int g = 0; g < 2; ++g) {
        const uint32_t* w4 = (const uint32_t*)&u[g];
#pragma unroll
        for (int j = 0; j < 4; ++j) {
            float2 t = __bfloat1622float2(*(const __nv_bfloat162*)&w4[j]);
            f[g * 8 + j * 2]     = t.x;
            f[g * 8 + j * 2 + 1] = t.y;
        }
    }

    const float sv = selfv[row];
    float m = -3.4e38f;
#pragma unroll
    for (int i = 0; i < 16; ++i) m = fmaxf(m, f[i]);
#pragma unroll
    for (int o = 16; o; o >>= 1) m = fmaxf(m, __shfl_xor_sync(0xffffffffu, m, o));

    __shared__ float smax[8], ssum[8], sbc[2];
    if (lane == 0) smax[wid] = m;
    __syncthreads();
    if (tid == 0) {
        float mm = sv;
#pragma unroll
        for (int i = 0; i < 8; ++i) mm = fmaxf(mm, smax[i]);
        sbc[0] = mm;
    }
    __syncthreads();
    m = sbc[0];

    const float invT = 0.044194173824159216f;  // 1/sqrt(512)
    float s = 0.f;
#pragma unroll
    for (int i = 0; i < 16; ++i) {
        f[i] = __expf((f[i] - m) * invT);
        s += f[i];
    }
#pragma unroll
    for (int o = 16; o; o >>= 1) s += __shfl_xor_sync(0xffffffffu, s, o);
    if (lane == 0) ssum[wid] = s;
    __syncthreads();
    if (tid == 0) {
        float es  = __expf((sv - m) * invT);
        float tot = es;
#pragma unroll
        for (int i = 0; i < 8; ++i) tot += ssum[i];
        sbc[1]  = 1.f / tot;
        w0[row] = es / tot;
    }
    __syncthreads();
    const float invZ = sbc[1];

#pragma unroll
    for (int g = 0; g < 2; ++g) {
        uint32_t* w4 = (uint32_t*)&u[g];
#pragma unroll
        for (int j = 0; j < 4; ++j) {
            __nv_bfloat162 h = __floats2bfloat162_rn(f[g * 8 + j * 2] * invZ,
                                                     f[g * 8 + j * 2 + 1] * invZ);
            w4[j] = *(const uint32_t*)&h;
        }
    }
    p[tid]       = u[0];
    p[tid + 256] = u[1];
}

// ---------------------------------------------------------------------------
// Epilogue: x = (O0+O1) + w0*Vv + v_code; out = LayerNorm(x)*gamma + beta
// Vv read as bf16 from QKV (offset 1024, stride 1536).
// ---------------------------------------------------------------------------
__global__ __launch_bounds__(128) void ln_residual(
    const float* __restrict__ O0, const float* __restrict__ O1,
    const __nv_bfloat16* __restrict__ QKV,
    const float* __restrict__ vcode, const float* __restrict__ w0,
    const float* __restrict__ gamma, const float* __restrict__ beta,
    float* __restrict__ out)
{
    const int row  = blockIdx.x;
    const int tid  = threadIdx.x;
    const int lane = tid & 31, wid = tid >> 5;
    const size_t base = (size_t)row * EE_ + tid * 4;
    const float w = w0[row];

    float4 o0 = *(const float4*)(O0 + base);
    float4 o1 = *(const float4*)(O1 + base);
    uint2 vvu = *(const uint2*)(QKV + (size_t)row * 1536 + 1024 + tid * 4);
    float2 v01 = __bfloat1622float2(*(const __nv_bfloat162*)&vvu.x);
    float2 v23 = __bfloat1622float2(*(const __nv_bfloat162*)&vvu.y);
    float4 vc = *(const float4*)(vcode + base);
    float4 x;
    x.x = fmaf(w, v01.x, o0.x + o1.x) + vc.x;
    x.y = fmaf(w, v01.y, o0.y + o1.y) + vc.y;
    x.z = fmaf(w, v23.x, o0.z + o1.z) + vc.z;
    x.w = fmaf(w, v23.y, o0.w + o1.w) + vc.w;

    __shared__ float sred[4];
    float s = x.x + x.y + x.z + x.w;
#pragma unroll
    for (int o2 = 16; o2; o2 >>= 1) s += __shfl_xor_sync(0xffffffffu, s, o2);
    if (lane == 0) sred[wid] = s;
    __syncthreads();
    const float mu = (sred[0] + sred[1] + sred[2] + sred[3]) * (1.f / 512.f);

    float4 d;
    d.x = x.x - mu; d.y = x.y - mu; d.z = x.z - mu; d.w = x.w - mu;
    float s2 = d.x * d.x + d.y * d.y + d.z * d.z + d.w * d.w;
#pragma unroll
    for (int o2 = 16; o2; o2 >>= 1) s2 += __shfl_xor_sync(0xffffffffu, s2, o2);
    __syncthreads();
    if (lane == 0) sred[wid] = s2;
    __syncthreads();
    const float var = (sred[0] + sred[1] + sred[2] + sred[3]) * (1.f / 512.f);
    const float r = rsqrtf(var + 1e-6f);

    float4 g4 = *(const float4*)(gamma + tid * 4);
    float4 b4 = *(const float4*)(beta + tid * 4);
    float4 y;
    y.x = fmaf(d.x * r, g4.x, b4.x);
    y.y = fmaf(d.y * r, g4.y, b4.y);
    y.z = fmaf(d.z * r, g4.z, b4.z);
    y.w = fmaf(d.w * r, g4.w, b4.w);
    *(float4*)(out + base) = y;
}

// ---------------------------------------------------------------------------
extern "C" void kernel_launch(void* const* d_in, const int* in_sizes, int n_in,
                              void* d_out, int out_size)
{
    const float* v_code   = (const float*)d_in[0];
    const float* obs_code = (const float*)d_in[1];
    const float* Wq       = (const float*)d_in[2];
    const float* Wk       = (const float*)d_in[3];
    const float* Wv       = (const float*)d_in[4];
    const float* gamma    = (const float*)d_in[5];
    const float* beta     = (const float*)d_in[6];
    float* out = (float*)d_out;

    __nv_bfloat16 *vcb, *obb, *Wcat, *QKV, *KoVo, *VoT, *S;
    float *Opart, *selfv, *w0;
    cudaGetSymbolAddress((void**)&vcb,   g_vcode_bf);
    cudaGetSymbolAddress((void**)&obb,   g_obs_bf);
    cudaGetSymbolAddress((void**)&Wcat,  g_Wcat);
    cudaGetSymbolAddress((void**)&QKV,   g_QKV);
    cudaGetSymbolAddress((void**)&KoVo,  g_KoVo);
    cudaGetSymbolAddress((void**)&VoT,   g_VoT);
    cudaGetSymbolAddress((void**)&S,     g_S);
    cudaGetSymbolAddress((void**)&Opart, g_Opart);
    cudaGetSymbolAddress((void**)&selfv, g_self);
    cudaGetSymbolAddress((void**)&w0,    g_w0);
    float* O0 = Opart;
    float* O1 = Opart + (size_t)NN_ * EE_;

    cudaFuncSetAttribute(gemm_nt<__nv_bfloat16>,
                         cudaFuncAttributeMaxDynamicSharedMemorySize, G_SMEM_TOTAL);
    cudaFuncSetAttribute(gemm_nt<float>,
                         cudaFuncAttributeMaxDynamicSharedMemorySize, G_SMEM_TOTAL);

    // bf16 conversions (weights into one concatenated [Wq;Wk;Wv] buffer)
    cvt_bf16<<<(NN_ * EE_ / 4 + 255) / 256, 256>>>(v_code,   vcb, NN_ * EE_ / 4);
    cvt_bf16<<<(MM_ * EE_ / 4 + 255) / 256, 256>>>(obs_code, obb, MM_ * EE_ / 4);
    cvt_bf16<<<(EE_ * EE_ / 4 + 255) / 256, 256>>>(Wq, Wcat,                 EE_ * EE_ / 4);
    cvt_bf16<<<(EE_ * EE_ / 4 + 255) / 256, 256>>>(Wk, Wcat + EE_ * EE_,     EE_ * EE_ / 4);
    cvt_bf16<<<(EE_ * EE_ / 4 + 255) / 256, 256>>>(Wv, Wcat + 2 * EE_ * EE_, EE_ * EE_ / 4);

    // QKV = v_code @ [Wq;Wk;Wv]^T   [8192, 1536]
    gemm_nt<__nv_bfloat16><<<dim3(1536/GBN, NN_/GBM), 256, G_SMEM_TOTAL>>>(
        vcb, Wcat, QKV, NN_, 1536, EE_, EE_, EE_, 1536, 0);
    // KoVo = obs_code @ [Wk;Wv]^T   [4096, 1024]
    gemm_nt<__nv_bfloat16><<<dim3(1024/GBN, MM_/GBM), 256, G_SMEM_TOTAL>>>(
        obb, Wcat + EE_ * EE_, KoVo, MM_, 1024, EE_, EE_, EE_, 1024, 0);

    // VoT = Vo^T  [512, 4096]
    transpose_vo<<<dim3(MM_ / 32, EE_ / 32), 256>>>(KoVo, VoT);

    // Self (diagonal) score
    diag_dot<<<NN_ / 8, 256>>>(QKV, selfv);

    // S = Q @ Ko^T  [8192, 4096]
    gemm_nt<__nv_bfloat16><<<dim3(MM_/GBN, NN_/GBM), 256, G_SMEM_TOTAL>>>(
        QKV, KoVo, S, NN_, MM_, EE_, 1536, 1024, MM_, 0);

    // Softmax rows (bf16 in-place), produce w0
    softmax_rows<<<NN_, 256>>>(S, selfv, w0);

    // O = P @ VoT^T  [8192, 512], split-K=2 via grid.z, fp32 partials
    gemm_nt<float><<<dim3(EE_/GBN, NN_/GBM, 2), 256, G_SMEM_TOTAL>>>(
        S, VoT, O0, NN_, EE_, MM_ / 2, MM_, MM_, EE_, MM_ / 2);

    // Residual + self-value + LayerNorm
    ln_residual<<<NN_, 128>>>(O0, O1, QKV, v_code, w0, gamma, beta, out);
}

// round 10
// speedup vs baseline: 7.3046x; 1.0393x over previous
#include <cuda_runtime.h>
#include <cuda_bf16.h>
#include <cstdint>
#include <cstddef>

#define NN_ 8192
#define MM_ 4096
#define EE_ 512

// ---------------- scratch (__device__ globals; no allocation) ----------------
__device__ __nv_bfloat16 g_vcode_bf[NN_ * EE_];
__device__ __nv_bfloat16 g_obs_bf  [MM_ * EE_];
__device__ __nv_bfloat16 g_Wcat    [3 * EE_ * EE_];         // [Wq; Wk; Wv]
__device__ __nv_bfloat16 g_QKV     [(size_t)NN_ * 3 * EE_]; // cols: Q|Kv|Vv
__device__ __nv_bfloat16 g_KoVo    [(size_t)MM_ * 2 * EE_]; // cols: Ko|Vo
__device__ __nv_bfloat16 g_VoT     [EE_ * MM_];             // [E, M]
__device__ __nv_bfloat16 g_S       [(size_t)NN_ * MM_];     // exp-weights (unnorm)
__device__ float         g_Zpart   [64 * NN_];              // [16 bx][4 wn][row]
__device__ float         g_Opart   [2][(size_t)NN_ * EE_];  // split-K partials

// ------------------------------- PTX helpers -------------------------------
__device__ __forceinline__ uint32_t smem_u32(const void* p) {
    uint32_t a;
    asm("{ .reg .u64 t; cvta.to.shared.u64 t, %1; cvt.u32.u64 %0, t; }"
        : "=r"(a) : "l"(p));
    return a;
}
__device__ __forceinline__ void cp16(uint32_t smem, const void* gmem) {
    asm volatile("cp.async.cg.shared.global [%0], [%1], 16;\n" :: "r"(smem), "l"(gmem));
}
#define CP_COMMIT() asm volatile("cp.async.commit_group;\n" ::: "memory")

__device__ __forceinline__ void ldm_x4(uint32_t& r0, uint32_t& r1,
                                       uint32_t& r2, uint32_t& r3, uint32_t addr) {
    asm volatile("ldmatrix.sync.aligned.m8n8.x4.shared.b16 {%0,%1,%2,%3}, [%4];"
                 : "=r"(r0), "=r"(r1), "=r"(r2), "=r"(r3) : "r"(addr));
}
__device__ __forceinline__ uint32_t swz(uint32_t off) {
    return off ^ ((off >> 3) & 0x70);
}
__device__ __forceinline__ void store_pair(float* p, float x, float y) {
    *(float2*)p = make_float2(x, y);
}
__device__ __forceinline__ void store_pair(__nv_bfloat16* p, float x, float y) {
    *(__nv_bfloat162*)p = __floats2bfloat162_rn(x, y);
}

// ---------------------------------------------------------------------------
// bf16 NT GEMM body (mma.sync): C[.,N] tile = A * B^T, fp32 acc.
// CTA tile 128x256x64, warp tile 64x64, 4-stage cp.async, 256 threads.
// DOEXP: epilogue stores exp(acc*invT) bf16 + per-warp row-sum partials.
// ---------------------------------------------------------------------------
#define GBM 128
#define GBN 256
#define GBK 64
#define A_STG 16384                      // 128 rows * 128B
#define B_STG 32768                      // 256 rows * 128B
#define STG_B (A_STG + B_STG)            // 49152
#define G_SMEM_TOTAL (4 * STG_B)         // 196608

template <typename OutT, bool DOEXP>
__device__ __forceinline__ void gemm_body(
    const __nv_bfloat16* __restrict__ A,
    const __nv_bfloat16* __restrict__ B,
    OutT* __restrict__ C,
    int lda, int ldb, int ldc, int KT,
    int row0, int col0,
    float* __restrict__ Zpart, int zbase)
{
    extern __shared__ char smem[];
    const uint32_t sb = smem_u32(smem);

    const int tid  = threadIdx.x;
    const int wid  = tid >> 5, lane = tid & 31;
    const int wm   = (wid >> 2) * 64;   // 0/64
    const int wnI  = wid & 3;
    const int wn   = wnI * 64;          // 0/64/128/192
    const int gID  = lane >> 2;
    const int tID  = lane & 3;

    const int lr = lane & 7;
    const int lm = lane >> 3;
    uint32_t baseA[4], baseB[4];
#pragma unroll
    for (int mi = 0; mi < 4; ++mi)
        baseA[mi] = (uint32_t)(wm + mi * 16 + (lm & 1) * 8 + lr) * 128 + (lm >> 1) * 16;
#pragma unroll
    for (int nj = 0; nj < 4; ++nj)
        baseB[nj] = (uint32_t)(wn + nj * 16 + (lm >> 1) * 8 + lr) * 128 + (lm & 1) * 16;

    auto load_stage = [&](int s, int k0) {
        const uint32_t abase = sb + s * STG_B;
#pragma unroll
        for (int i = 0; i < 4; ++i) {      // A: 1024 16B chunks
            int idx = tid + 256 * i;
            int r = idx >> 3, ck = idx & 7;
            cp16(abase + swz(r * 128 + ck * 16),
                 A + (size_t)(row0 + r) * lda + k0 + ck * 8);
        }
        const uint32_t bbase = abase + A_STG;
#pragma unroll
        for (int i = 0; i < 8; ++i) {      // B: 2048 16B chunks
            int idx = tid + 256 * i;
            int r = idx >> 3, ck = idx & 7;
            cp16(bbase + swz(r * 128 + ck * 16),
                 B + (size_t)(col0 + r) * ldb + k0 + ck * 8);
        }
        CP_COMMIT();
    };

    float acc[4][8][4];
#pragma unroll
    for (int mi = 0; mi < 4; ++mi)
#pragma unroll
        for (int ni = 0; ni < 8; ++ni)
#pragma unroll
            for (int q = 0; q < 4; ++q) acc[mi][ni][q] = 0.f;

    load_stage(0, 0);
    load_stage(1, GBK);
    load_stage(2, 2 * GBK);

    for (int kt = 0; kt < KT; ++kt) {
        const int s = kt & 3;
        if (kt <= KT - 3)      asm volatile("cp.async.wait_group 2;\n" ::: "memory");
        else if (kt == KT - 2) asm volatile("cp.async.wait_group 1;\n" ::: "memory");
        else                   asm volatile("cp.async.wait_group 0;\n" ::: "memory");
        __syncthreads();
        if (kt + 3 < KT) load_stage((kt + 3) & 3, (kt + 3) * GBK);

        const uint32_t Ab = sb + s * STG_B;
        const uint32_t Bb = Ab + A_STG;
#pragma unroll
        for (int kb = 0; kb < 4; ++kb) {
            const uint32_t ko = kb * 32;
            uint32_t a[4][4], b[4][4];
#pragma unroll
            for (int mi = 0; mi < 4; ++mi)
                ldm_x4(a[mi][0], a[mi][1], a[mi][2], a[mi][3],
                       Ab + swz(baseA[mi] + ko));
#pragma unroll
            for (int nj = 0; nj < 4; ++nj)
                ldm_x4(b[nj][0], b[nj][1], b[nj][2], b[nj][3],
                       Bb + swz(baseB[nj] + ko));
#pragma unroll
            for (int mi = 0; mi < 4; ++mi) {
#pragma unroll
                for (int ni = 0; ni < 8; ++ni) {
                    const uint32_t b0 = b[ni >> 1][(ni & 1) * 2];
                    const uint32_t b1 = b[ni >> 1][(ni & 1) * 2 + 1];
                    asm volatile(
                        "mma.sync.aligned.m16n8k16.row.col.f32.bf16.bf16.f32 "
                        "{%0,%1,%2,%3}, {%4,%5,%6,%7}, {%8,%9}, {%0,%1,%2,%3};\n"
                        : "+f"(acc[mi][ni][0]), "+f"(acc[mi][ni][1]),
                          "+f"(acc[mi][ni][2]), "+f"(acc[mi][ni][3])
                        : "r"(a[mi][0]), "r"(a[mi][1]), "r"(a[mi][2]), "r"(a[mi][3]),
                          "r"(b0), "r"(b1));
                }
            }
        }
        __syncthreads();
    }

    if constexpr (DOEXP) {
        // exp epilogue: store exp(acc*invT) bf16 + per-warp row-sum partials.
        const float invT = 0.044194173824159216f;  // 1/sqrt(512)
#pragma unroll
        for (int mi = 0; mi < 4; ++mi) {
            const int r  = row0 + wm + mi * 16 + gID;
            float s0 = 0.f, s1 = 0.f;
#pragma unroll
            for (int ni = 0; ni < 8; ++ni) {
                const int cc = col0 + wn + ni * 8 + tID * 2;
                float e0 = __expf(acc[mi][ni][0] * invT);
                float e1 = __expf(acc[mi][ni][1] * invT);
                float e2 = __expf(acc[mi][ni][2] * invT);
                float e3 = __expf(acc[mi][ni][3] * invT);
                s0 += e0 + e1;
                s1 += e2 + e3;
                store_pair((__nv_bfloat16*)C + (size_t)r * ldc + cc,       e0, e1);
                store_pair((__nv_bfloat16*)C + (size_t)(r + 8) * ldc + cc, e2, e3);
            }
            // reduce over the 4 tID lanes sharing this row
            s0 += __shfl_xor_sync(0xffffffffu, s0, 1);
            s0 += __shfl_xor_sync(0xffffffffu, s0, 2);
            s1 += __shfl_xor_sync(0xffffffffu, s1, 1);
            s1 += __shfl_xor_sync(0xffffffffu, s1, 2);
            if (tID == 0) {
                Zpart[(size_t)(zbase + wnI) * NN_ + r]     = s0;
                Zpart[(size_t)(zbase + wnI) * NN_ + r + 8] = s1;
            }
        }
    } else {
#pragma unroll
        for (int mi = 0; mi < 4; ++mi) {
#pragma unroll
            for (int ni = 0; ni < 8; ++ni) {
                const int r  = row0 + wm + mi * 16 + gID;
                const int cc = col0 + wn + ni * 8 + tID * 2;
                store_pair(C + (size_t)r * ldc + cc,       acc[mi][ni][0], acc[mi][ni][1]);
                store_pair(C + (size_t)(r + 8) * ldc + cc, acc[mi][ni][2], acc[mi][ni][3]);
            }
        }
    }
}

// ---------------------------------------------------------------------------
// Merged projections: bid<384 -> QKV = v_code @ Wcat^T  (8192x1536)
//                     else    -> KoVo = obs_code @ [Wk;Wv]^T (4096x1024)
// ---------------------------------------------------------------------------
__global__ __launch_bounds__(256, 1) void proj_gemm(
    const __nv_bfloat16* __restrict__ vcb,
    const __nv_bfloat16* __restrict__ obb,
    const __nv_bfloat16* __restrict__ Wcat,
    __nv_bfloat16* __restrict__ QKV,
    __nv_bfloat16* __restrict__ KoVo)
{
    const int bid = blockIdx.x;
    if (bid < 384) {
        const int bx = bid % 6, by = bid / 6;
        gemm_body<__nv_bfloat16, false>(vcb, Wcat, QKV,
                                        EE_, EE_, 1536, EE_ / GBK,
                                        by * GBM, bx * GBN, nullptr, 0);
    } else {
        const int b2 = bid - 384;
        const int bx = b2 % 4, by = b2 / 4;
        gemm_body<__nv_bfloat16, false>(obb, Wcat + EE_ * EE_, KoVo,
                                        EE_, EE_, 1024, EE_ / GBK,
                                        by * GBM, bx * GBN, nullptr, 0);
    }
}

// S = exp((Q @ Ko^T)/T) (unnormalized) + Zpart row sums
__global__ __launch_bounds__(256, 1) void score_gemm(
    const __nv_bfloat16* __restrict__ QKV,
    const __nv_bfloat16* __restrict__ KoVo,
    __nv_bfloat16* __restrict__ S, float* __restrict__ Zpart)
{
    gemm_body<__nv_bfloat16, true>(QKV, KoVo, S,
                                   1536, 1024, MM_, EE_ / GBK,
                                   blockIdx.y * GBM, blockIdx.x * GBN,
                                   Zpart, blockIdx.x * 4);
}

// O partials = expS @ VoT^T, split-K=2 via grid.z
__global__ __launch_bounds__(256, 1) void out_gemm(
    const __nv_bfloat16* __restrict__ S,
    const __nv_bfloat16* __restrict__ VoT,
    float* __restrict__ O)
{
    const int kz = blockIdx.z;
    gemm_body<float, false>(S + (size_t)kz * (MM_ / 2),
                            VoT + (size_t)kz * (MM_ / 2),
                            O + (size_t)kz * NN_ * EE_,
                            MM_, MM_, EE_, (MM_ / 2) / GBK,
                            blockIdx.y * GBM, blockIdx.x * GBN, nullptr, 0);
}

// ---------------------------------------------------------------------------
// float -> bf16 conversion, 4 elems/thread
// ---------------------------------------------------------------------------
__global__ void cvt_bf16(const float* __restrict__ in,
                         __nv_bfloat16* __restrict__ out, int n4)
{
    int i = blockIdx.x * blockDim.x + threadIdx.x;
    if (i < n4) {
        float4 v = ((const float4*)in)[i];
        ((__nv_bfloat162*)out)[2 * i]     = __floats2bfloat162_rn(v.x, v.y);
        ((__nv_bfloat162*)out)[2 * i + 1] = __floats2bfloat162_rn(v.z, v.w);
    }
}

// ---------------------------------------------------------------------------
// Transpose Vo (cols 512..1023 of KoVo [4096, 1024]) -> VoT [512, 4096]
// ---------------------------------------------------------------------------
__global__ __launch_bounds__(256) void transpose_vo(
    const __nv_bfloat16* __restrict__ KoVo, __nv_bfloat16* __restrict__ VoT)
{
    __shared__ __nv_bfloat16 t[32][33];
    const int tx = threadIdx.x & 31, ty = threadIdx.x >> 5;  // 32x8
    const int m0 = blockIdx.x * 32;
    const int e0 = blockIdx.y * 32;
#pragma unroll
    for (int p = 0; p < 4; ++p)
        t[ty + p * 8][tx] = KoVo[(size_t)(m0 + ty + p * 8) * 1024 + 512 + e0 + tx];
    __syncthreads();
#pragma unroll
    for (int p = 0; p < 4; ++p)
        VoT[(size_t)(e0 + ty + p * 8) * MM_ + m0 + tx] = t[tx][ty + p * 8];
}

// ---------------------------------------------------------------------------
// Epilogue (fused): sv = Q.Kv diag; Z = sum Zpart + exp(sv/T);
// x = (O0+O1)/Ztot + w0*Vv + v_code;  out = LayerNorm(x)*gamma + beta
// ---------------------------------------------------------------------------
__global__ __launch_bounds__(128) void ln_residual(
    const float* __restrict__ O0, const float* __restrict__ O1,
    const __nv_bfloat16* __restrict__ QKV,
    const float* __restrict__ Zpart,
    const float* __restrict__ vcode,
    const float* __restrict__ gamma, const float* __restrict__ beta,
    float* __restrict__ out)
{
    const int row  = blockIdx.x;
    const int tid  = threadIdx.x;
    const int lane = tid & 31, wid = tid >> 5;
    const size_t base = (size_t)row * EE_ + tid * 4;

    // self score partial: dot(Q[row], Kv[row]) over 4 elems/thread
    uint2 qu  = *(const uint2*)(QKV + (size_t)row * 1536 + tid * 4);
    uint2 ku  = *(const uint2*)(QKV + (size_t)row * 1536 + 512 + tid * 4);
    float2 q01 = __bfloat1622float2(*(const __nv_bfloat162*)&qu.x);
    float2 q23 = __bfloat1622float2(*(const __nv_bfloat162*)&qu.y);
    float2 k01 = __bfloat1622float2(*(const __nv_bfloat162*)&ku.x);
    float2 k23 = __bfloat1622float2(*(const __nv_bfloat162*)&ku.y);
    float svp = q01.x * k01.x + q01.y * k01.y + q23.x * k23.x + q23.y * k23.y;
    float zp  = (tid < 64) ? Zpart[(size_t)tid * NN_ + row] : 0.f;

    __shared__ float sA[4], sB[4];
#pragma unroll
    for (int o = 16; o; o >>= 1) {
        svp += __shfl_xor_sync(0xffffffffu, svp, o);
        zp  += __shfl_xor_sync(0xffffffffu, zp, o);
    }
    if (lane == 0) { sA[wid] = svp; sB[wid] = zp; }
    __syncthreads();
    const float sv = sA[0] + sA[1] + sA[2] + sA[3];
    const float Z  = sB[0] + sB[1] + sB[2] + sB[3];

    const float invT = 0.044194173824159216f;
    const float es   = __expf(sv * invT);
    const float invZ = 1.f / (Z + es);
    const float w    = es * invZ;

    float4 o0 = *(const float4*)(O0 + base);
    float4 o1 = *(const float4*)(O1 + base);
    uint2 vvu = *(const uint2*)(QKV + (size_t)row * 1536 + 1024 + tid * 4);
    float2 v01 = __bfloat1622float2(*(const __nv_bfloat162*)&vvu.x);
    float2 v23 = __bfloat1622float2(*(const __nv_bfloat162*)&vvu.y);
    float4 vc = *(const float4*)(vcode + base);
    float4 x;
    x.x = fmaf(w, v01.x, (o0.x + o1.x) * invZ) + vc.x;
    x.y = fmaf(w, v01.y, (o0.y + o1.y) * invZ) + vc.y;
    x.z = fmaf(w, v23.x, (o0.z + o1.z) * invZ) + vc.z;
    x.w = fmaf(w, v23.y, (o0.w + o1.w) * invZ) + vc.w;

    __shared__ float sred[4];
    float s = x.x + x.y + x.z + x.w;
#pragma unroll
    for (int o2 = 16; o2; o2 >>= 1) s += __shfl_xor_sync(0xffffffffu, s, o2);
    if (lane == 0) sred[wid] = s;
    __syncthreads();
    const float mu = (sred[0] + sred[1] + sred[2] + sred[3]) * (1.f / 512.f);

    float4 d;
    d.x = x.x - mu; d.y = x.y - mu; d.z = x.z - mu; d.w = x.w - mu;
    float s2 = d.x * d.x + d.y * d.y + d.z * d.z + d.w * d.w;
#pragma unroll
    for (int o2 = 16; o2; o2 >>= 1) s2 += __shfl_xor_sync(0xffffffffu, s2, o2);
    __syncthreads();
    if (lane == 0) sred[wid] = s2;
    __syncthreads();
    const float var = (sred[0] + sred[1] + sred[2] + sred[3]) * (1.f / 512.f);
    const float r = rsqrtf(var + 1e-6f);

    float4 g4 = *(const float4*)(gamma + tid * 4);
    float4 b4 = *(const float4*)(beta + tid * 4);
    float4 y;
    y.x = fmaf(d.x * r, g4.x, b4.x);
    y.y = fmaf(d.y * r, g4.y, b4.y);
    y.z = fmaf(d.z * r, g4.z, b4.z);
    y.w = fmaf(d.w * r, g4.w, b4.w);
    *(float4*)(out + base) = y;
}

// ---------------------------------------------------------------------------
extern "C" void kernel_launch(void* const* d_in, const int* in_sizes, int n_in,
                              void* d_out, int out_size)
{
    const float* v_code   = (const float*)d_in[0];
    const float* obs_code = (const float*)d_in[1];
    const float* Wq       = (const float*)d_in[2];
    const float* Wk       = (const float*)d_in[3];
    const float* Wv       = (const float*)d_in[4];
    const float* gamma    = (const float*)d_in[5];
    const float* beta     = (const float*)d_in[6];
    float* out = (float*)d_out;

    __nv_bfloat16 *vcb, *obb, *Wcat, *QKV, *KoVo, *VoT, *S;
    float *Opart, *Zpart;
    cudaGetSymbolAddress((void**)&vcb,   g_vcode_bf);
    cudaGetSymbolAddress((void**)&obb,   g_obs_bf);
    cudaGetSymbolAddress((void**)&Wcat,  g_Wcat);
    cudaGetSymbolAddress((void**)&QKV,   g_QKV);
    cudaGetSymbolAddress((void**)&KoVo,  g_KoVo);
    cudaGetSymbolAddress((void**)&VoT,   g_VoT);
    cudaGetSymbolAddress((void**)&S,     g_S);
    cudaGetSymbolAddress((void**)&Opart, g_Opart);
    cudaGetSymbolAddress((void**)&Zpart, g_Zpart);
    float* O0 = Opart;
    float* O1 = Opart + (size_t)NN_ * EE_;

    cudaFuncSetAttribute(proj_gemm,  cudaFuncAttributeMaxDynamicSharedMemorySize, G_SMEM_TOTAL);
    cudaFuncSetAttribute(score_gemm, cudaFuncAttributeMaxDynamicSharedMemorySize, G_SMEM_TOTAL);
    cudaFuncSetAttribute(out_gemm,   cudaFuncAttributeMaxDynamicSharedMemorySize, G_SMEM_TOTAL);

    // bf16 conversions (weights into one concatenated [Wq;Wk;Wv] buffer)
    cvt_bf16<<<(NN_ * EE_ / 4 + 255) / 256, 256>>>(v_code,   vcb, NN_ * EE_ / 4);
    cvt_bf16<<<(MM_ * EE_ / 4 + 255) / 256, 256>>>(obs_code, obb, MM_ * EE_ / 4);
    cvt_bf16<<<(EE_ * EE_ / 4 + 255) / 256, 256>>>(Wq, Wcat,                 EE_ * EE_ / 4);
    cvt_bf16<<<(EE_ * EE_ / 4 + 255) / 256, 256>>>(Wk, Wcat + EE_ * EE_,     EE_ * EE_ / 4);
    cvt_bf16<<<(EE_ * EE_ / 4 + 255) / 256, 256>>>(Wv, Wcat + 2 * EE_ * EE_, EE_ * EE_ / 4);

    // Merged projections: QKV (384 CTAs) + KoVo (128 CTAs)
    proj_gemm<<<512, 256, G_SMEM_TOTAL>>>(vcb, obb, Wcat, QKV, KoVo);

    // VoT = Vo^T  [512, 4096]
    transpose_vo<<<dim3(MM_ / 32, EE_ / 32), 256>>>(KoVo, VoT);

    // S = exp((Q @ Ko^T)/T) unnormalized [8192, 4096] + Zpart
    score_gemm<<<dim3(MM_ / GBN, NN_ / GBM), 256, G_SMEM_TOTAL>>>(QKV, KoVo, S, Zpart);

    // O partials = expS @ VoT^T, split-K=2
    out_gemm<<<dim3(EE_ / GBN, NN_ / GBM, 2), 256, G_SMEM_TOTAL>>>(S, VoT, O0);

    // Fused: self score + normalization + residual + LayerNorm
    ln_residual<<<NN_, 128>>>(O0, O1, QKV, Zpart, v_code, gamma, beta, out);
}

// round 14
// speedup vs baseline: 7.4265x; 1.0167x over previous
#include <cuda_runtime.h>
#include <cuda_bf16.h>
#include <cstdint>
#include <cstddef>

#define NN_ 8192
#define MM_ 4096
#define EE_ 512

// ---------------- scratch (__device__ globals; no allocation) ----------------
__device__ __nv_bfloat16 g_vcode_bf[NN_ * EE_];
__device__ __nv_bfloat16 g_obs_bf  [MM_ * EE_];
__device__ __nv_bfloat16 g_Wcat    [3 * EE_ * EE_];         // [Wq; Wk; Wv]
__device__ __nv_bfloat16 g_QKV     [(size_t)NN_ * 3 * EE_]; // cols: Q|Kv|Vv
__device__ __nv_bfloat16 g_KoVo    [(size_t)MM_ * 2 * EE_]; // cols: Ko|Vo
__device__ __nv_bfloat16 g_VoT     [EE_ * MM_];             // [E, M]
__device__ __nv_bfloat16 g_S       [(size_t)NN_ * MM_];     // exp-weights (unnorm)
__device__ float         g_Zpart   [64 * NN_];              // [16 bx][4 wn][row]
__device__ float         g_Opart   [2][(size_t)NN_ * EE_];  // split-K partials

// ------------------------------- PTX helpers -------------------------------
__device__ __forceinline__ uint32_t smem_u32(const void* p) {
    uint32_t a;
    asm("{ .reg .u64 t; cvta.to.shared.u64 t, %1; cvt.u32.u64 %0, t; }"
        : "=r"(a) : "l"(p));
    return a;
}
__device__ __forceinline__ void cp16(uint32_t smem, const void* gmem) {
    asm volatile("cp.async.cg.shared.global [%0], [%1], 16;\n" :: "r"(smem), "l"(gmem));
}
#define CP_COMMIT() asm volatile("cp.async.commit_group;\n" ::: "memory")

__device__ __forceinline__ void ldm_x4(uint32_t& r0, uint32_t& r1,
                                       uint32_t& r2, uint32_t& r3, uint32_t addr) {
    asm volatile("ldmatrix.sync.aligned.m8n8.x4.shared.b16 {%0,%1,%2,%3}, [%4];"
                 : "=r"(r0), "=r"(r1), "=r"(r2), "=r"(r3) : "r"(addr));
}
__device__ __forceinline__ uint32_t swz(uint32_t off) {
    return off ^ ((off >> 3) & 0x70);
}
__device__ __forceinline__ void store_pair(float* p, float x, float y) {
    *(float2*)p = make_float2(x, y);
}
__device__ __forceinline__ void store_pair(__nv_bfloat16* p, float x, float y) {
    *(__nv_bfloat162*)p = __floats2bfloat162_rn(x, y);
}

// ---------------------------------------------------------------------------
// bf16 NT GEMM body (mma.sync): C[.,N] tile = A * B^T, fp32 acc.
// CTA tile 128x256x64, warp tile 64x64, 4-stage cp.async, 256 threads.
// Register double-buffered ldmatrix fragments (prefetch kb+1 during kb MMAs).
// DOEXP: epilogue stores exp(acc*invT) bf16 + per-warp row-sum partials.
// ---------------------------------------------------------------------------
#define GBM 128
#define GBN 256
#define GBK 64
#define A_STG 16384                      // 128 rows * 128B
#define B_STG 32768                      // 256 rows * 128B
#define STG_B (A_STG + B_STG)            // 49152
#define G_SMEM_TOTAL (4 * STG_B)         // 196608

template <typename OutT, bool DOEXP>
__device__ __forceinline__ void gemm_body(
    const __nv_bfloat16* __restrict__ A,
    const __nv_bfloat16* __restrict__ B,
    OutT* __restrict__ C,
    int lda, int ldb, int ldc, int KT,
    int row0, int col0,
    float* __restrict__ Zpart, int zbase)
{
    extern __shared__ char smem[];
    const uint32_t sb = smem_u32(smem);

    const int tid  = threadIdx.x;
    const int wid  = tid >> 5, lane = tid & 31;
    const int wm   = (wid >> 2) * 64;   // 0/64
    const int wnI  = wid & 3;
    const int wn   = wnI * 64;          // 0/64/128/192
    const int gID  = lane >> 2;
    const int tID  = lane & 3;

    const int lr = lane & 7;
    const int lm = lane >> 3;
    uint32_t baseA[4], baseB[4];
#pragma unroll
    for (int mi = 0; mi < 4; ++mi)
        baseA[mi] = (uint32_t)(wm + mi * 16 + (lm & 1) * 8 + lr) * 128 + (lm >> 1) * 16;
#pragma unroll
    for (int nj = 0; nj < 4; ++nj)
        baseB[nj] = (uint32_t)(wn + nj * 16 + (lm >> 1) * 8 + lr) * 128 + (lm & 1) * 16;

    auto load_stage = [&](int s, int k0) {
        const uint32_t abase = sb + s * STG_B;
#pragma unroll
        for (int i = 0; i < 4; ++i) {      // A: 1024 16B chunks
            int idx = tid + 256 * i;
            int r = idx >> 3, ck = idx & 7;
            cp16(abase + swz(r * 128 + ck * 16),
                 A + (size_t)(row0 + r) * lda + k0 + ck * 8);
        }
        const uint32_t bbase = abase + A_STG;
#pragma unroll
        for (int i = 0; i < 8; ++i) {      // B: 2048 16B chunks
            int idx = tid + 256 * i;
            int r = idx >> 3, ck = idx & 7;
            cp16(bbase + swz(r * 128 + ck * 16),
                 B + (size_t)(col0 + r) * ldb + k0 + ck * 8);
        }
        CP_COMMIT();
    };

    float acc[4][8][4];
#pragma unroll
    for (int mi = 0; mi < 4; ++mi)
#pragma unroll
        for (int ni = 0; ni < 8; ++ni)
#pragma unroll
            for (int q = 0; q < 4; ++q) acc[mi][ni][q] = 0.f;

    load_stage(0, 0);
    load_stage(1, GBK);
    load_stage(2, 2 * GBK);

    uint32_t a[2][4][4], b[2][4][4];

    for (int kt = 0; kt < KT; ++kt) {
        const int s = kt & 3;
        if (kt <= KT - 3)      asm volatile("cp.async.wait_group 2;\n" ::: "memory");
        else if (kt == KT - 2) asm volatile("cp.async.wait_group 1;\n" ::: "memory");
        else                   asm volatile("cp.async.wait_group 0;\n" ::: "memory");
        __syncthreads();
        if (kt + 3 < KT) load_stage((kt + 3) & 3, (kt + 3) * GBK);

        const uint32_t Ab = sb + s * STG_B;
        const uint32_t Bb = Ab + A_STG;

        // prime kb=0 fragments into buffer 0
#pragma unroll
        for (int mi = 0; mi < 4; ++mi)
            ldm_x4(a[0][mi][0], a[0][mi][1], a[0][mi][2], a[0][mi][3],
                   Ab + swz(baseA[mi]));
#pragma unroll
        for (int nj = 0; nj < 4; ++nj)
            ldm_x4(b[0][nj][0], b[0][nj][1], b[0][nj][2], b[0][nj][3],
                   Bb + swz(baseB[nj]));

#pragma unroll
        for (int kb = 0; kb < 4; ++kb) {
            const int cur = kb & 1, nxt = cur ^ 1;
            if (kb < 3) {                  // prefetch kb+1 while kb MMAs run
                const uint32_t ko = (kb + 1) * 32;
#pragma unroll
                for (int mi = 0; mi < 4; ++mi)
                    ldm_x4(a[nxt][mi][0], a[nxt][mi][1], a[nxt][mi][2], a[nxt][mi][3],
                           Ab + swz(baseA[mi] + ko));
#pragma unroll
                for (int nj = 0; nj < 4; ++nj)
                    ldm_x4(b[nxt][nj][0], b[nxt][nj][1], b[nxt][nj][2], b[nxt][nj][3],
                           Bb + swz(baseB[nj] + ko));
            }
#pragma unroll
            for (int mi = 0; mi < 4; ++mi) {
#pragma unroll
                for (int ni = 0; ni < 8; ++ni) {
                    const uint32_t b0 = b[cur][ni >> 1][(ni & 1) * 2];
                    const uint32_t b1 = b[cur][ni >> 1][(ni & 1) * 2 + 1];
                    asm volatile(
                        "mma.sync.aligned.m16n8k16.row.col.f32.bf16.bf16.f32 "
                        "{%0,%1,%2,%3}, {%4,%5,%6,%7}, {%8,%9}, {%0,%1,%2,%3};\n"
                        : "+f"(acc[mi][ni][0]), "+f"(acc[mi][ni][1]),
                          "+f"(acc[mi][ni][2]), "+f"(acc[mi][ni][3])
                        : "r"(a[cur][mi][0]), "r"(a[cur][mi][1]),
                          "r"(a[cur][mi][2]), "r"(a[cur][mi][3]),
                          "r"(b0), "r"(b1));
                }
            }
        }
        __syncthreads();
    }

    if constexpr (DOEXP) {
        // exp epilogue: store exp(acc*invT) bf16 + per-warp row-sum partials.
        const float invT = 0.044194173824159216f;  // 1/sqrt(512)
#pragma unroll
        for (int mi = 0; mi < 4; ++mi) {
            const int r  = row0 + wm + mi * 16 + gID;
            float s0 = 0.f, s1 = 0.f;
#pragma unroll
            for (int ni = 0; ni < 8; ++ni) {
                const int cc = col0 + wn + ni * 8 + tID * 2;
                float e0 = __expf(acc[mi][ni][0] * invT);
                float e1 = __expf(acc[mi][ni][1] * invT);
                float e2 = __expf(acc[mi][ni][2] * invT);
                float e3 = __expf(acc[mi][ni][3] * invT);
                s0 += e0 + e1;
                s1 += e2 + e3;
                store_pair((__nv_bfloat16*)C + (size_t)r * ldc + cc,       e0, e1);
                store_pair((__nv_bfloat16*)C + (size_t)(r + 8) * ldc + cc, e2, e3);
            }
            s0 += __shfl_xor_sync(0xffffffffu, s0, 1);
            s0 += __shfl_xor_sync(0xffffffffu, s0, 2);
            s1 += __shfl_xor_sync(0xffffffffu, s1, 1);
            s1 += __shfl_xor_sync(0xffffffffu, s1, 2);
            if (tID == 0) {
                Zpart[(size_t)(zbase + wnI) * NN_ + r]     = s0;
                Zpart[(size_t)(zbase + wnI) * NN_ + r + 8] = s1;
            }
        }
    } else {
#pragma unroll
        for (int mi = 0; mi < 4; ++mi) {
#pragma unroll
            for (int ni = 0; ni < 8; ++ni) {
                const int r  = row0 + wm + mi * 16 + gID;
                const int cc = col0 + wn + ni * 8 + tID * 2;
                store_pair(C + (size_t)r * ldc + cc,       acc[mi][ni][0], acc[mi][ni][1]);
                store_pair(C + (size_t)(r + 8) * ldc + cc, acc[mi][ni][2], acc[mi][ni][3]);
            }
        }
    }
}

// ---------------------------------------------------------------------------
// Merged projections: bid<384 -> QKV = v_code @ Wcat^T  (8192x1536)
//                     else    -> KoVo = obs_code @ [Wk;Wv]^T (4096x1024)
// ---------------------------------------------------------------------------
__global__ __launch_bounds__(256, 1) void proj_gemm(
    const __nv_bfloat16* __restrict__ vcb,
    const __nv_bfloat16* __restrict__ obb,
    const __nv_bfloat16* __restrict__ Wcat,
    __nv_bfloat16* __restrict__ QKV,
    __nv_bfloat16* __restrict__ KoVo)
{
    const int bid = blockIdx.x;
    if (bid < 384) {
        const int bx = bid % 6, by = bid / 6;
        gemm_body<__nv_bfloat16, false>(vcb, Wcat, QKV,
                                        EE_, EE_, 1536, EE_ / GBK,
                                        by * GBM, bx * GBN, nullptr, 0);
    } else {
        const int b2 = bid - 384;
        const int bx = b2 % 4, by = b2 / 4;
        gemm_body<__nv_bfloat16, false>(obb, Wcat + EE_ * EE_, KoVo,
                                        EE_, EE_, 1024, EE_ / GBK,
                                        by * GBM, bx * GBN, nullptr, 0);
    }
}

// S = exp((Q @ Ko^T)/T) (unnormalized) + Zpart row sums
__global__ __launch_bounds__(256, 1) void score_gemm(
    const __nv_bfloat16* __restrict__ QKV,
    const __nv_bfloat16* __restrict__ KoVo,
    __nv_bfloat16* __restrict__ S, float* __restrict__ Zpart)
{
    gemm_body<__nv_bfloat16, true>(QKV, KoVo, S,
                                   1536, 1024, MM_, EE_ / GBK,
                                   blockIdx.y * GBM, blockIdx.x * GBN,
                                   Zpart, blockIdx.x * 4);
}

// O partials = expS @ VoT^T, split-K=2 via grid.z
__global__ __launch_bounds__(256, 1) void out_gemm(
    const __nv_bfloat16* __restrict__ S,
    const __nv_bfloat16* __restrict__ VoT,
    float* __restrict__ O)
{
    const int kz = blockIdx.z;
    gemm_body<float, false>(S + (size_t)kz * (MM_ / 2),
                            VoT + (size_t)kz * (MM_ / 2),
                            O + (size_t)kz * NN_ * EE_,
                            MM_, MM_, EE_, (MM_ / 2) / GBK,
                            blockIdx.y * GBM, blockIdx.x * GBN, nullptr, 0);
}

// ---------------------------------------------------------------------------
// Merged float -> bf16 conversion for all 5 inputs, 4 elems/thread
// ---------------------------------------------------------------------------
#define CVT_N_VC (NN_ * EE_ / 4)                 // 1048576
#define CVT_N_OB (MM_ * EE_ / 4)                 // 524288
#define CVT_N_W  (EE_ * EE_ / 4)                 // 65536
#define CVT_TOTAL (CVT_N_VC + CVT_N_OB + 3 * CVT_N_W)

__global__ __launch_bounds__(256) void cvt_all(
    const float* __restrict__ v_code, const float* __restrict__ obs_code,
    const float* __restrict__ Wq, const float* __restrict__ Wk,
    const float* __restrict__ Wv,
    __nv_bfloat16* __restrict__ vcb, __nv_bfloat16* __restrict__ obb,
    __nv_bfloat16* __restrict__ Wcat)
{
    int i = blockIdx.x * blockDim.x + threadIdx.x;
    if (i >= CVT_TOTAL) return;
    const float* src;
    __nv_bfloat16* dst;
    int j = i;
    if (j < CVT_N_VC) { src = v_code; dst = vcb; }
    else if ((j -= CVT_N_VC) < CVT_N_OB) { src = obs_code; dst = obb; }
    else if ((j -= CVT_N_OB) < CVT_N_W) { src = Wq; dst = Wcat; }
    else if ((j -= CVT_N_W) < CVT_N_W)  { src = Wk; dst = Wcat + EE_ * EE_; }
    else { j -= CVT_N_W; src = Wv; dst = Wcat + 2 * EE_ * EE_; }
    float4 v = ((const float4*)src)[j];
    ((__nv_bfloat162*)dst)[2 * j]     = __floats2bfloat162_rn(v.x, v.y);
    ((__nv_bfloat162*)dst)[2 * j + 1] = __floats2bfloat162_rn(v.z, v.w);
}

// ---------------------------------------------------------------------------
// Transpose Vo (cols 512..1023 of KoVo [4096, 1024]) -> VoT [512, 4096]
// ---------------------------------------------------------------------------
__global__ __launch_bounds__(256) void transpose_vo(
    const __nv_bfloat16* __restrict__ KoVo, __nv_bfloat16* __restrict__ VoT)
{
    __shared__ __nv_bfloat16 t[32][33];
    const int tx = threadIdx.x & 31, ty = threadIdx.x >> 5;  // 32x8
    const int m0 = blockIdx.x * 32;
    const int e0 = blockIdx.y * 32;
#pragma unroll
    for (int p = 0; p < 4; ++p)
        t[ty + p * 8][tx] = KoVo[(size_t)(m0 + ty + p * 8) * 1024 + 512 + e0 + tx];
    __syncthreads();
#pragma unroll
    for (int p = 0; p < 4; ++p)
        VoT[(size_t)(e0 + ty + p * 8) * MM_ + m0 + tx] = t[tx][ty + p * 8];
}

// ---------------------------------------------------------------------------
// Epilogue (fused): sv = Q.Kv diag; Z = sum Zpart + exp(sv/T);
// x = (O0+O1)/Ztot + w0*Vv + v_code;  out = LayerNorm(x)*gamma + beta
// ---------------------------------------------------------------------------
__global__ __launch_bounds__(128) void ln_residual(
    const float* __restrict__ O0, const float* __restrict__ O1,
    const __nv_bfloat16* __restrict__ QKV,
    const float* __restrict__ Zpart,
    const float* __restrict__ vcode,
    const float* __restrict__ gamma, const float* __restrict__ beta,
    float* __restrict__ out)
{
    const int row  = blockIdx.x;
    const int tid  = threadIdx.x;
    const int lane = tid & 31, wid = tid >> 5;
    const size_t base = (size_t)row * EE_ + tid * 4;

    uint2 qu  = *(const uint2*)(QKV + (size_t)row * 1536 + tid * 4);
    uint2 ku  = *(const uint2*)(QKV + (size_t)row * 1536 + 512 + tid * 4);
    float2 q01 = __bfloat1622float2(*(const __nv_bfloat162*)&qu.x);
    float2 q23 = __bfloat1622float2(*(const __nv_bfloat162*)&qu.y);
    float2 k01 = __bfloat1622float2(*(const __nv_bfloat162*)&ku.x);
    float2 k23 = __bfloat1622float2(*(const __nv_bfloat162*)&ku.y);
    float svp = q01.x * k01.x + q01.y * k01.y + q23.x * k23.x + q23.y * k23.y;
    float zp  = (tid < 64) ? Zpart[(size_t)tid * NN_ + row] : 0.f;

    __shared__ float sA[4], sB[4];
#pragma unroll
    for (int o = 16; o; o >>= 1) {
        svp += __shfl_xor_sync(0xffffffffu, svp, o);
        zp  += __shfl_xor_sync(0xffffffffu, zp, o);
    }
    if (lane == 0) { sA[wid] = svp; sB[wid] = zp; }
    __syncthreads();
    const float sv = sA[0] + sA[1] + sA[2] + sA[3];
    const float Z  = sB[0] + sB[1] + sB[2] + sB[3];

    const float invT = 0.044194173824159216f;
    const float es   = __expf(sv * invT);
    const float invZ = 1.f / (Z + es);
    const float w    = es * invZ;

    float4 o0 = *(const float4*)(O0 + base);
    float4 o1 = *(const float4*)(O1 + base);
    uint2 vvu = *(const uint2*)(QKV + (size_t)row * 1536 + 1024 + tid * 4);
    float2 v01 = __bfloat1622float2(*(const __nv_bfloat162*)&vvu.x);
    float2 v23 = __bfloat1622float2(*(const __nv_bfloat162*)&vvu.y);
    float4 vc = *(const float4*)(vcode + base);
    float4 x;
    x.x = fmaf(w, v01.x, (o0.x + o1.x) * invZ) + vc.x;
    x.y = fmaf(w, v01.y, (o0.y + o1.y) * invZ) + vc.y;
    x.z = fmaf(w, v23.x, (o0.z + o1.z) * invZ) + vc.z;
    x.w = fmaf(w, v23.y, (o0.w + o1.w) * invZ) + vc.w;

    __shared__ float sred[4];
    float s = x.x + x.y + x.z + x.w;
#pragma unroll
    for (int o2 = 16; o2; o2 >>= 1) s += __shfl_xor_sync(0xffffffffu, s, o2);
    if (lane == 0) sred[wid] = s;
    __syncthreads();
    const float mu = (sred[0] + sred[1] + sred[2] + sred[3]) * (1.f / 512.f);

    float4 d;
    d.x = x.x - mu; d.y = x.y - mu; d.z = x.z - mu; d.w = x.w - mu;
    float s2 = d.x * d.x + d.y * d.y + d.z * d.z + d.w * d.w;
#pragma unroll
    for (int o2 = 16; o2; o2 >>= 1) s2 += __shfl_xor_sync(0xffffffffu, s2, o2);
    __syncthreads();
    if (lane == 0) sred[wid] = s2;
    __syncthreads();
    const float var = (sred[0] + sred[1] + sred[2] + sred[3]) * (1.f / 512.f);
    const float r = rsqrtf(var + 1e-6f);

    float4 g4 = *(const float4*)(gamma + tid * 4);
    float4 b4 = *(const float4*)(beta + tid * 4);
    float4 y;
    y.x = fmaf(d.x * r, g4.x, b4.x);
    y.y = fmaf(d.y * r, g4.y, b4.y);
    y.z = fmaf(d.z * r, g4.z, b4.z);
    y.w = fmaf(d.w * r, g4.w, b4.w);
    *(float4*)(out + base) = y;
}

// ---------------------------------------------------------------------------
extern "C" void kernel_launch(void* const* d_in, const int* in_sizes, int n_in,
                              void* d_out, int out_size)
{
    const float* v_code   = (const float*)d_in[0];
    const float* obs_code = (const float*)d_in[1];
    const float* Wq       = (const float*)d_in[2];
    const float* Wk       = (const float*)d_in[3];
    const float* Wv       = (const float*)d_in[4];
    const float* gamma    = (const float*)d_in[5];
    const float* beta     = (const float*)d_in[6];
    float* out = (float*)d_out;

    __nv_bfloat16 *vcb, *obb, *Wcat, *QKV, *KoVo, *VoT, *S;
    float *Opart, *Zpart;
    cudaGetSymbolAddress((void**)&vcb,   g_vcode_bf);
    cudaGetSymbolAddress((void**)&obb,   g_obs_bf);
    cudaGetSymbolAddress((void**)&Wcat,  g_Wcat);
    cudaGetSymbolAddress((void**)&QKV,   g_QKV);
    cudaGetSymbolAddress((void**)&KoVo,  g_KoVo);
    cudaGetSymbolAddress((void**)&VoT,   g_VoT);
    cudaGetSymbolAddress((void**)&S,     g_S);
    cudaGetSymbolAddress((void**)&Opart, g_Opart);
    cudaGetSymbolAddress((void**)&Zpart, g_Zpart);
    float* O0 = Opart;
    float* O1 = Opart + (size_t)NN_ * EE_;

    cudaFuncSetAttribute(proj_gemm,  cudaFuncAttributeMaxDynamicSharedMemorySize, G_SMEM_TOTAL);
    cudaFuncSetAttribute(score_gemm, cudaFuncAttributeMaxDynamicSharedMemorySize, G_SMEM_TOTAL);
    cudaFuncSetAttribute(out_gemm,   cudaFuncAttributeMaxDynamicSharedMemorySize, G_SMEM_TOTAL);

    // One merged bf16 conversion launch for all 5 inputs
    cvt_all<<<(CVT_TOTAL + 255) / 256, 256>>>(v_code, obs_code, Wq, Wk, Wv,
                                              vcb, obb, Wcat);

    // Merged projections: QKV (384 CTAs) + KoVo (128 CTAs)
    proj_gemm<<<512, 256, G_SMEM_TOTAL>>>(vcb, obb, Wcat, QKV, KoVo);

    // VoT = Vo^T  [512, 4096]
    transpose_vo<<<dim3(MM_ / 32, EE_ / 32), 256>>>(KoVo, VoT);

    // S = exp((Q @ Ko^T)/T) unnormalized [8192, 4096] + Zpart
    score_gemm<<<dim3(MM_ / GBN, NN_ / GBM), 256, G_SMEM_TOTAL>>>(QKV, KoVo, S, Zpart);

    // O partials = expS @ VoT^T, split-K=2
    out_gemm<<<dim3(EE_ / GBN, NN_ / GBM, 2), 256, G_SMEM_TOTAL>>>(S, VoT, O0);

    // Fused: self score + normalization + residual + LayerNorm
    ln_residual<<<NN_, 128>>>(O0, O1, QKV, Zpart, v_code, gamma, beta, out);
}

// round 15
// speedup vs baseline: 7.4429x; 1.0022x over previous
#include <cuda_runtime.h>
#include <cuda_bf16.h>
#include <cstdint>
#include <cstddef>

#define NN_ 8192
#define MM_ 4096
#define EE_ 512

// ---------------- scratch (__device__ globals; no allocation) ----------------
__device__ __nv_bfloat16 g_vcode_bf[NN_ * EE_];
__device__ __nv_bfloat16 g_obs_bf  [MM_ * EE_];
__device__ __nv_bfloat16 g_Wcat    [3 * EE_ * EE_];         // [Wq; Wk; Wv]
__device__ __nv_bfloat16 g_QKV     [(size_t)NN_ * 3 * EE_]; // cols: Q|Kv|Vv
__device__ __nv_bfloat16 g_KoVo    [(size_t)MM_ * 2 * EE_]; // cols: Ko|Vo
__device__ __nv_bfloat16 g_VoT     [EE_ * MM_];             // [E, M]
__device__ __nv_bfloat16 g_S       [(size_t)NN_ * MM_];     // exp-weights (unnorm)
__device__ float         g_Zpart   [128 * NN_];             // [16 bx][8 wn][row]
__device__ float         g_Opart   [2][(size_t)NN_ * EE_];  // split-K partials

// ------------------------------- PTX helpers -------------------------------
__device__ __forceinline__ uint32_t smem_u32(const void* p) {
    uint32_t a;
    asm("{ .reg .u64 t; cvta.to.shared.u64 t, %1; cvt.u32.u64 %0, t; }"
        : "=r"(a) : "l"(p));
    return a;
}
__device__ __forceinline__ void cp16(uint32_t smem, const void* gmem) {
    asm volatile("cp.async.cg.shared.global [%0], [%1], 16;\n" :: "r"(smem), "l"(gmem));
}
#define CP_COMMIT() asm volatile("cp.async.commit_group;\n" ::: "memory")

__device__ __forceinline__ void ldm_x4(uint32_t& r0, uint32_t& r1,
                                       uint32_t& r2, uint32_t& r3, uint32_t addr) {
    asm volatile("ldmatrix.sync.aligned.m8n8.x4.shared.b16 {%0,%1,%2,%3}, [%4];"
                 : "=r"(r0), "=r"(r1), "=r"(r2), "=r"(r3) : "r"(addr));
}
__device__ __forceinline__ uint32_t swz(uint32_t off) {
    return off ^ ((off >> 3) & 0x70);
}
__device__ __forceinline__ void store_pair(float* p, float x, float y) {
    *(float2*)p = make_float2(x, y);
}
__device__ __forceinline__ void store_pair(__nv_bfloat16* p, float x, float y) {
    *(__nv_bfloat162*)p = __floats2bfloat162_rn(x, y);
}

// ---------------------------------------------------------------------------
// bf16 NT GEMM body (mma.sync): C tile = A * B^T, fp32 acc.
// CTA tile 128x256x64, 512 threads (16 warps, warp tile 64x32),
// 4-stage cp.async, single __syncthreads per k-tile.
// DOEXP: epilogue stores exp(acc*invT) bf16 + per-warp row-sum partials.
// ---------------------------------------------------------------------------
#define GBM 128
#define GBN 256
#define GBK 64
#define GTHREADS 512
#define A_STG 16384                      // 128 rows * 128B
#define B_STG 32768                      // 256 rows * 128B
#define STG_B (A_STG + B_STG)            // 49152
#define G_SMEM_TOTAL (4 * STG_B)         // 196608

template <typename OutT, bool DOEXP>
__device__ __forceinline__ void gemm_body(
    const __nv_bfloat16* __restrict__ A,
    const __nv_bfloat16* __restrict__ B,
    OutT* __restrict__ C,
    int lda, int ldb, int ldc, int KT,
    int row0, int col0,
    float* __restrict__ Zpart, int zbase)
{
    extern __shared__ char smem[];
    const uint32_t sb = smem_u32(smem);

    const int tid  = threadIdx.x;
    const int wid  = tid >> 5, lane = tid & 31;
    const int wm   = (wid >> 3) * 64;   // 0/64
    const int wnI  = wid & 7;
    const int wn   = wnI * 32;          // 0..224
    const int gID  = lane >> 2;
    const int tID  = lane & 3;

    const int lr = lane & 7;
    const int lm = lane >> 3;
    uint32_t baseA[4], baseB[2];
#pragma unroll
    for (int mi = 0; mi < 4; ++mi)
        baseA[mi] = (uint32_t)(wm + mi * 16 + (lm & 1) * 8 + lr) * 128 + (lm >> 1) * 16;
#pragma unroll
    for (int nj = 0; nj < 2; ++nj)
        baseB[nj] = (uint32_t)(wn + nj * 16 + (lm >> 1) * 8 + lr) * 128 + (lm & 1) * 16;

    auto load_stage = [&](int s, int k0) {
        const uint32_t abase = sb + s * STG_B;
#pragma unroll
        for (int i = 0; i < 2; ++i) {      // A: 1024 16B chunks / 512 thr
            int idx = tid + GTHREADS * i;
            int r = idx >> 3, ck = idx & 7;
            cp16(abase + swz(r * 128 + ck * 16),
                 A + (size_t)(row0 + r) * lda + k0 + ck * 8);
        }
        const uint32_t bbase = abase + A_STG;
#pragma unroll
        for (int i = 0; i < 4; ++i) {      // B: 2048 16B chunks / 512 thr
            int idx = tid + GTHREADS * i;
            int r = idx >> 3, ck = idx & 7;
            cp16(bbase + swz(r * 128 + ck * 16),
                 B + (size_t)(col0 + r) * ldb + k0 + ck * 8);
        }
        CP_COMMIT();
    };

    float acc[4][4][4];
#pragma unroll
    for (int mi = 0; mi < 4; ++mi)
#pragma unroll
        for (int ni = 0; ni < 4; ++ni)
#pragma unroll
            for (int q = 0; q < 4; ++q) acc[mi][ni][q] = 0.f;

    load_stage(0, 0);
    load_stage(1, GBK);
    load_stage(2, 2 * GBK);

    for (int kt = 0; kt < KT; ++kt) {
        const int s = kt & 3;
        if (kt <= KT - 3)      asm volatile("cp.async.wait_group 2;\n" ::: "memory");
        else if (kt == KT - 2) asm volatile("cp.async.wait_group 1;\n" ::: "memory");
        else                   asm volatile("cp.async.wait_group 0;\n" ::: "memory");
        __syncthreads();
        if (kt + 3 < KT) load_stage((kt + 3) & 3, (kt + 3) * GBK);

        const uint32_t Ab = sb + s * STG_B;
        const uint32_t Bb = Ab + A_STG;
#pragma unroll
        for (int kb = 0; kb < 4; ++kb) {
            const uint32_t ko = kb * 32;
            uint32_t a[4][4], b[2][4];
#pragma unroll
            for (int mi = 0; mi < 4; ++mi)
                ldm_x4(a[mi][0], a[mi][1], a[mi][2], a[mi][3],
                       Ab + swz(baseA[mi] + ko));
#pragma unroll
            for (int nj = 0; nj < 2; ++nj)
                ldm_x4(b[nj][0], b[nj][1], b[nj][2], b[nj][3],
                       Bb + swz(baseB[nj] + ko));
#pragma unroll
            for (int mi = 0; mi < 4; ++mi) {
#pragma unroll
                for (int ni = 0; ni < 4; ++ni) {
                    const uint32_t b0 = b[ni >> 1][(ni & 1) * 2];
                    const uint32_t b1 = b[ni >> 1][(ni & 1) * 2 + 1];
                    asm volatile(
                        "mma.sync.aligned.m16n8k16.row.col.f32.bf16.bf16.f32 "
                        "{%0,%1,%2,%3}, {%4,%5,%6,%7}, {%8,%9}, {%0,%1,%2,%3};\n"
                        : "+f"(acc[mi][ni][0]), "+f"(acc[mi][ni][1]),
                          "+f"(acc[mi][ni][2]), "+f"(acc[mi][ni][3])
                        : "r"(a[mi][0]), "r"(a[mi][1]), "r"(a[mi][2]), "r"(a[mi][3]),
                          "r"(b0), "r"(b1));
                }
            }
        }
        // NOTE: no trailing __syncthreads — next iteration's wait+sync is the
        // barrier; stage written at kt ((kt-1)&3) is protected because all
        // threads passed the sync after completing kt-1's MMAs.
    }

    if constexpr (DOEXP) {
        const float invT = 0.044194173824159216f;  // 1/sqrt(512)
#pragma unroll
        for (int mi = 0; mi < 4; ++mi) {
            const int r  = row0 + wm + mi * 16 + gID;
            float s0 = 0.f, s1 = 0.f;
#pragma unroll
            for (int ni = 0; ni < 4; ++ni) {
                const int cc = col0 + wn + ni * 8 + tID * 2;
                float e0 = __expf(acc[mi][ni][0] * invT);
                float e1 = __expf(acc[mi][ni][1] * invT);
                float e2 = __expf(acc[mi][ni][2] * invT);
                float e3 = __expf(acc[mi][ni][3] * invT);
                s0 += e0 + e1;
                s1 += e2 + e3;
                store_pair((__nv_bfloat16*)C + (size_t)r * ldc + cc,       e0, e1);
                store_pair((__nv_bfloat16*)C + (size_t)(r + 8) * ldc + cc, e2, e3);
            }
            s0 += __shfl_xor_sync(0xffffffffu, s0, 1);
            s0 += __shfl_xor_sync(0xffffffffu, s0, 2);
            s1 += __shfl_xor_sync(0xffffffffu, s1, 1);
            s1 += __shfl_xor_sync(0xffffffffu, s1, 2);
            if (tID == 0) {
                Zpart[(size_t)(zbase + wnI) * NN_ + r]     = s0;
                Zpart[(size_t)(zbase + wnI) * NN_ + r + 8] = s1;
            }
        }
    } else {
#pragma unroll
        for (int mi = 0; mi < 4; ++mi) {
#pragma unroll
            for (int ni = 0; ni < 4; ++ni) {
                const int r  = row0 + wm + mi * 16 + gID;
                const int cc = col0 + wn + ni * 8 + tID * 2;
                store_pair(C + (size_t)r * ldc + cc,       acc[mi][ni][0], acc[mi][ni][1]);
                store_pair(C + (size_t)(r + 8) * ldc + cc, acc[mi][ni][2], acc[mi][ni][3]);
            }
        }
    }
}

// ---------------------------------------------------------------------------
// Merged projections: bid<384 -> QKV = v_code @ Wcat^T  (8192x1536)
//                     else    -> KoVo = obs_code @ [Wk;Wv]^T (4096x1024)
// ---------------------------------------------------------------------------
__global__ __launch_bounds__(GTHREADS, 1) void proj_gemm(
    const __nv_bfloat16* __restrict__ vcb,
    const __nv_bfloat16* __restrict__ obb,
    const __nv_bfloat16* __restrict__ Wcat,
    __nv_bfloat16* __restrict__ QKV,
    __nv_bfloat16* __restrict__ KoVo)
{
    const int bid = blockIdx.x;
    if (bid < 384) {
        const int bx = bid % 6, by = bid / 6;
        gemm_body<__nv_bfloat16, false>(vcb, Wcat, QKV,
                                        EE_, EE_, 1536, EE_ / GBK,
                                        by * GBM, bx * GBN, nullptr, 0);
    } else {
        const int b2 = bid - 384;
        const int bx = b2 % 4, by = b2 / 4;
        gemm_body<__nv_bfloat16, false>(obb, Wcat + EE_ * EE_, KoVo,
                                        EE_, EE_, 1024, EE_ / GBK,
                                        by * GBM, bx * GBN, nullptr, 0);
    }
}

// S = exp((Q @ Ko^T)/T) (unnormalized) + Zpart row sums
__global__ __launch_bounds__(GTHREADS, 1) void score_gemm(
    const __nv_bfloat16* __restrict__ QKV,
    const __nv_bfloat16* __restrict__ KoVo,
    __nv_bfloat16* __restrict__ S, float* __restrict__ Zpart)
{
    gemm_body<__nv_bfloat16, true>(QKV, KoVo, S,
                                   1536, 1024, MM_, EE_ / GBK,
                                   blockIdx.y * GBM, blockIdx.x * GBN,
                                   Zpart, blockIdx.x * 8);
}

// O partials = expS @ VoT^T, split-K=2 via grid.z
__global__ __launch_bounds__(GTHREADS, 1) void out_gemm(
    const __nv_bfloat16* __restrict__ S,
    const __nv_bfloat16* __restrict__ VoT,
    float* __restrict__ O)
{
    const int kz = blockIdx.z;
    gemm_body<float, false>(S + (size_t)kz * (MM_ / 2),
                            VoT + (size_t)kz * (MM_ / 2),
                            O + (size_t)kz * NN_ * EE_,
                            MM_, MM_, EE_, (MM_ / 2) / GBK,
                            blockIdx.y * GBM, blockIdx.x * GBN, nullptr, 0);
}

// ---------------------------------------------------------------------------
// Merged float -> bf16 conversion for all 5 inputs, 4 elems/thread
// ---------------------------------------------------------------------------
#define CVT_N_VC (NN_ * EE_ / 4)                 // 1048576
#define CVT_N_OB (MM_ * EE_ / 4)                 // 524288
#define CVT_N_W  (EE_ * EE_ / 4)                 // 65536
#define CVT_TOTAL (CVT_N_VC + CVT_N_OB + 3 * CVT_N_W)

__global__ __launch_bounds__(256) void cvt_all(
    const float* __restrict__ v_code, const float* __restrict__ obs_code,
    const float* __restrict__ Wq, const float* __restrict__ Wk,
    const float* __restrict__ Wv,
    __nv_bfloat16* __restrict__ vcb, __nv_bfloat16* __restrict__ obb,
    __nv_bfloat16* __restrict__ Wcat)
{
    int i = blockIdx.x * blockDim.x + threadIdx.x;
    if (i >= CVT_TOTAL) return;
    const float* src;
    __nv_bfloat16* dst;
    int j = i;
    if (j < CVT_N_VC) { src = v_code; dst = vcb; }
    else if ((j -= CVT_N_VC) < CVT_N_OB) { src = obs_code; dst = obb; }
    else if ((j -= CVT_N_OB) < CVT_N_W) { src = Wq; dst = Wcat; }
    else if ((j -= CVT_N_W) < CVT_N_W)  { src = Wk; dst = Wcat + EE_ * EE_; }
    else { j -= CVT_N_W; src = Wv; dst = Wcat + 2 * EE_ * EE_; }
    float4 v = ((const float4*)src)[j];
    ((__nv_bfloat162*)dst)[2 * j]     = __floats2bfloat162_rn(v.x, v.y);
    ((__nv_bfloat162*)dst)[2 * j + 1] = __floats2bfloat162_rn(v.z, v.w);
}

// ---------------------------------------------------------------------------
// Transpose Vo (cols 512..1023 of KoVo [4096, 1024]) -> VoT [512, 4096]
// ---------------------------------------------------------------------------
__global__ __launch_bounds__(256) void transpose_vo(
    const __nv_bfloat16* __restrict__ KoVo, __nv_bfloat16* __restrict__ VoT)
{
    __shared__ __nv_bfloat16 t[32][33];
    const int tx = threadIdx.x & 31, ty = threadIdx.x >> 5;  // 32x8
    const int m0 = blockIdx.x * 32;
    const int e0 = blockIdx.y * 32;
#pragma unroll
    for (int p = 0; p < 4; ++p)
        t[ty + p * 8][tx] = KoVo[(size_t)(m0 + ty + p * 8) * 1024 + 512 + e0 + tx];
    __syncthreads();
#pragma unroll
    for (int p = 0; p < 4; ++p)
        VoT[(size_t)(e0 + ty + p * 8) * MM_ + m0 + tx] = t[tx][ty + p * 8];
}

// ---------------------------------------------------------------------------
// Epilogue (fused): sv = Q.Kv diag; Z = sum Zpart(128) + exp(sv/T);
// x = (O0+O1)/Ztot + w0*Vv + v_code;  out = LayerNorm(x)*gamma + beta
// ---------------------------------------------------------------------------
__global__ __launch_bounds__(128) void ln_residual(
    const float* __restrict__ O0, const float* __restrict__ O1,
    const __nv_bfloat16* __restrict__ QKV,
    const float* __restrict__ Zpart,
    const float* __restrict__ vcode,
    const float* __restrict__ gamma, const float* __restrict__ beta,
    float* __restrict__ out)
{
    const int row  = blockIdx.x;
    const int tid  = threadIdx.x;
    const int lane = tid & 31, wid = tid >> 5;
    const size_t base = (size_t)row * EE_ + tid * 4;

    uint2 qu  = *(const uint2*)(QKV + (size_t)row * 1536 + tid * 4);
    uint2 ku  = *(const uint2*)(QKV + (size_t)row * 1536 + 512 + tid * 4);
    float2 q01 = __bfloat1622float2(*(const __nv_bfloat162*)&qu.x);
    float2 q23 = __bfloat1622float2(*(const __nv_bfloat162*)&qu.y);
    float2 k01 = __bfloat1622float2(*(const __nv_bfloat162*)&ku.x);
    float2 k23 = __bfloat1622float2(*(const __nv_bfloat162*)&ku.y);
    float svp = q01.x * k01.x + q01.y * k01.y + q23.x * k23.x + q23.y * k23.y;
    float zp  = Zpart[(size_t)tid * NN_ + row];

    __shared__ float sA[4], sB[4];
#pragma unroll
    for (int o = 16; o; o >>= 1) {
        svp += __shfl_xor_sync(0xffffffffu, svp, o);
        zp  += __shfl_xor_sync(0xffffffffu, zp, o);
    }
    if (lane == 0) { sA[wid] = svp; sB[wid] = zp; }
    __syncthreads();
    const float sv = sA[0] + sA[1] + sA[2] + sA[3];
    const float Z  = sB[0] + sB[1] + sB[2] + sB[3];

    const float invT = 0.044194173824159216f;
    const float es   = __expf(sv * invT);
    const float invZ = 1.f / (Z + es);
    const float w    = es * invZ;

    float4 o0 = *(const float4*)(O0 + base);
    float4 o1 = *(const float4*)(O1 + base);
    uint2 vvu = *(const uint2*)(QKV + (size_t)row * 1536 + 1024 + tid * 4);
    float2 v01 = __bfloat1622float2(*(const __nv_bfloat162*)&vvu.x);
    float2 v23 = __bfloat1622float2(*(const __nv_bfloat162*)&vvu.y);
    float4 vc = *(const float4*)(vcode + base);
    float4 x;
    x.x = fmaf(w, v01.x, (o0.x + o1.x) * invZ) + vc.x;
    x.y = fmaf(w, v01.y, (o0.y + o1.y) * invZ) + vc.y;
    x.z = fmaf(w, v23.x, (o0.z + o1.z) * invZ) + vc.z;
    x.w = fmaf(w, v23.y, (o0.w + o1.w) * invZ) + vc.w;

    __shared__ float sred[4];
    float s = x.x + x.y + x.z + x.w;
#pragma unroll
    for (int o2 = 16; o2; o2 >>= 1) s += __shfl_xor_sync(0xffffffffu, s, o2);
    if (lane == 0) sred[wid] = s;
    __syncthreads();
    const float mu = (sred[0] + sred[1] + sred[2] + sred[3]) * (1.f / 512.f);

    float4 d;
    d.x = x.x - mu; d.y = x.y - mu; d.z = x.z - mu; d.w = x.w - mu;
    float s2 = d.x * d.x + d.y * d.y + d.z * d.z + d.w * d.w;
#pragma unroll
    for (int o2 = 16; o2; o2 >>= 1) s2 += __shfl_xor_sync(0xffffffffu, s2, o2);
    __syncthreads();
    if (lane == 0) sred[wid] = s2;
    __syncthreads();
    const float var = (sred[0] + sred[1] + sred[2] + sred[3]) * (1.f / 512.f);
    const float r = rsqrtf(var + 1e-6f);

    float4 g4 = *(const float4*)(gamma + tid * 4);
    float4 b4 = *(const float4*)(beta + tid * 4);
    float4 y;
    y.x = fmaf(d.x * r, g4.x, b4.x);
    y.y = fmaf(d.y * r, g4.y, b4.y);
    y.z = fmaf(d.z * r, g4.z, b4.z);
    y.w = fmaf(d.w * r, g4.w, b4.w);
    *(float4*)(out + base) = y;
}

// ---------------------------------------------------------------------------
extern "C" void kernel_launch(void* const* d_in, const int* in_sizes, int n_in,
                              void* d_out, int out_size)
{
    const float* v_code   = (const float*)d_in[0];
    const float* obs_code = (const float*)d_in[1];
    const float* Wq       = (const float*)d_in[2];
    const float* Wk       = (const float*)d_in[3];
    const float* Wv       = (const float*)d_in[4];
    const float* gamma    = (const float*)d_in[5];
    const float* beta     = (const float*)d_in[6];
    float* out = (float*)d_out;

    __nv_bfloat16 *vcb, *obb, *Wcat, *QKV, *KoVo, *VoT, *S;
    float *Opart, *Zpart;
    cudaGetSymbolAddress((void**)&vcb,   g_vcode_bf);
    cudaGetSymbolAddress((void**)&obb,   g_obs_bf);
    cudaGetSymbolAddress((void**)&Wcat,  g_Wcat);
    cudaGetSymbolAddress((void**)&QKV,   g_QKV);
    cudaGetSymbolAddress((void**)&KoVo,  g_KoVo);
    cudaGetSymbolAddress((void**)&VoT,   g_VoT);
    cudaGetSymbolAddress((void**)&S,     g_S);
    cudaGetSymbolAddress((void**)&Opart, g_Opart);
    cudaGetSymbolAddress((void**)&Zpart, g_Zpart);
    float* O0 = Opart;
    float* O1 = Opart + (size_t)NN_ * EE_;

    cudaFuncSetAttribute(proj_gemm,  cudaFuncAttributeMaxDynamicSharedMemorySize, G_SMEM_TOTAL);
    cudaFuncSetAttribute(score_gemm, cudaFuncAttributeMaxDynamicSharedMemorySize, G_SMEM_TOTAL);
    cudaFuncSetAttribute(out_gemm,   cudaFuncAttributeMaxDynamicSharedMemorySize, G_SMEM_TOTAL);

    // One merged bf16 conversion launch for all 5 inputs
    cvt_all<<<(CVT_TOTAL + 255) / 256, 256>>>(v_code, obs_code, Wq, Wk, Wv,
                                              vcb, obb, Wcat);

    // Merged projections: QKV (384 CTAs) + KoVo (128 CTAs)
    proj_gemm<<<512, GTHREADS, G_SMEM_TOTAL>>>(vcb, obb, Wcat, QKV, KoVo);

    // VoT = Vo^T  [512, 4096]
    transpose_vo<<<dim3(MM_ / 32, EE_ / 32), 256>>>(KoVo, VoT);

    // S = exp((Q @ Ko^T)/T) unnormalized [8192, 4096] + Zpart
    score_gemm<<<dim3(MM_ / GBN, NN_ / GBM), GTHREADS, G_SMEM_TOTAL>>>(QKV, KoVo, S, Zpart);

    // O partials = expS @ VoT^T, split-K=2
    out_gemm<<<dim3(EE_ / GBN, NN_ / GBM, 2), GTHREADS, G_SMEM_TOTAL>>>(S, VoT, O0);

    // Fused: self score + normalization + residual + LayerNorm
    ln_residual<<<NN_, 128>>>(O0, O1, QKV, Zpart, v_code, gamma, beta, out);
}